// round 14
// baseline (speedup 1.0000x reference)
#include <cuda_runtime.h>
#include <cuda_fp16.h>
#include <cstdint>

#define NN 50000
#define EE 800000
#define ET (EE + NN)
#define D 128
#define HH 8
#define DVC 16
#define DHID 512
#define NEG 0.2f
#define BNEPS 1e-5f

// ---------------- scratch ----------------
__device__ float g_h[NN * D];
__device__ float g_tmp[NN * D];      // z1 -> h1(f32) -> h2pre (aliased, per-thread RAW safe)
__device__ float2 g_asf[NN * HH];    // (a_src, exp(a_src))
__device__ float2 g_adf[NN * HH];    // (a_dst, exp(a_dst))
__device__ float g_dinv[NN];
__device__ float g_sum[D];
__device__ float g_sumsq[D];
__device__ int g_cnt[NN];
__device__ int g_off[NN + 1];
__device__ int g_cur[NN];
__device__ int g_csr[ET];
__device__ __half g_h16[NN * D];             // h fp16 (xl GEMM A)
__device__ __half g_h116[NN * D];            // h1 fp16 (lin2 A)
__device__ __half g_hid16[NN * DHID];        // hidden fp16 (lin3 A)
// per-layer preconverted weights (transposed)
__device__ __half g_wxh[2 * D * D], g_wxl[2 * D * D];
__device__ __half g_w2h[2 * DHID * D];
__device__ __half g_w3h[2 * D * DHID];
__device__ __half g_xlh[NN * D];
__device__ __half g_ya[NN * D], g_yb[NN * D];

// ---------------- PTX helpers ----------------
__device__ __forceinline__ uint32_t sm32(const void* p) {
    uint32_t a;
    asm("{ .reg .u64 t; cvta.to.shared.u64 t, %1; cvt.u32.u64 %0, t; }" : "=r"(a) : "l"(p));
    return a;
}
__device__ __forceinline__ void cpasync16(uint32_t dst, const void* src, int srcsize) {
    asm volatile("cp.async.ca.shared.global [%0], [%1], 16, %2;"
                 :: "r"(dst), "l"(src), "r"(srcsize));
}
__device__ __forceinline__ void cpcommit() {
    asm volatile("cp.async.commit_group;" ::: "memory");
}
template <int N>
__device__ __forceinline__ void cpwait() {
    asm volatile("cp.async.wait_group %0;" :: "n"(N) : "memory");
}
__device__ __forceinline__ void ldsm4(uint32_t* r, uint32_t addr) {
    asm volatile("ldmatrix.sync.aligned.m8n8.x4.shared.b16 {%0,%1,%2,%3}, [%4];"
                 : "=r"(r[0]), "=r"(r[1]), "=r"(r[2]), "=r"(r[3]) : "r"(addr));
}
__device__ __forceinline__ void mma16816h(float* c, const uint32_t* a, const uint32_t* b) {
    asm volatile(
        "mma.sync.aligned.m16n8k16.row.col.f32.f16.f16.f32 "
        "{%0,%1,%2,%3}, {%4,%5,%6,%7}, {%8,%9}, {%0,%1,%2,%3};"
        : "+f"(c[0]), "+f"(c[1]), "+f"(c[2]), "+f"(c[3])
        : "r"(a[0]), "r"(a[1]), "r"(a[2]), "r"(a[3]), "r"(b[0]), "r"(b[1]));
}

// ---------------- CSR construction ----------------
__global__ void k_count(const int* __restrict__ ei) {
    int e = blockIdx.x * blockDim.x + threadIdx.x;
    if (e < EE) atomicAdd(&g_cnt[ei[EE + e]], 1);
}

__global__ void k_scan() {
    __shared__ int warp_sums[32];
    __shared__ int s_carry;
    int t = threadIdx.x;
    int lane = t & 31, wid = t >> 5;
    if (t == 0) { s_carry = 0; g_off[0] = 0; }
    __syncthreads();
    for (int base = 0; base < NN; base += 1024) {
        int i = base + t;
        int v = (i < NN) ? (g_cnt[i] + 1) : 0;
        int x = v;
        #pragma unroll
        for (int d = 1; d < 32; d <<= 1) {
            int y = __shfl_up_sync(0xFFFFFFFFu, x, d);
            if (lane >= d) x += y;
        }
        if (lane == 31) warp_sums[wid] = x;
        __syncthreads();
        if (wid == 0) {
            int w = warp_sums[lane];
            #pragma unroll
            for (int d = 1; d < 32; d <<= 1) {
                int y = __shfl_up_sync(0xFFFFFFFFu, w, d);
                if (lane >= d) w += y;
            }
            warp_sums[lane] = w;
        }
        __syncthreads();
        int incl = x + (wid > 0 ? warp_sums[wid - 1] : 0) + s_carry;
        if (i < NN) g_off[i + 1] = incl;
        __syncthreads();
        if (t == 1023) s_carry = incl;
        __syncthreads();
    }
    for (int i = t; i < NN; i += 1024) {
        int o0 = g_off[i], o1 = g_off[i + 1];
        g_cur[i] = o0;
        g_dinv[i] = rsqrtf((float)(o1 - o0));
    }
}

__global__ void k_fill(const int* __restrict__ ei) {
    int idx = blockIdx.x * blockDim.x + threadIdx.x;
    if (idx >= ET) return;
    int s, d;
    if (idx < EE) { s = ei[idx]; d = ei[EE + idx]; }
    else { s = idx - EE; d = s; }
    int pos = atomicAdd(&g_cur[d], 1);
    g_csr[pos] = s;
}

// ---------------- lin0 (+ zero cnt) ----------------
__global__ void k_lin0(const float* __restrict__ x, const float* __restrict__ J,
                       const float* __restrict__ w, const float* __restrict__ b) {
    int i = blockIdx.x * blockDim.x + threadIdx.x;
    if (i < NN) g_cnt[i] = 0;
    if (i >= NN * D) return;
    int n = i >> 7, d = i & 127;
    float v = x[n * 2] * w[d] + x[n * 2 + 1] * w[D + d] + J[n] * w[2 * D + d] + b[d];
    g_h[i] = v;
    g_h16[i] = __float2half(v);
}

// ---------------- all weights preconvert + transpose (one kernel) ----------------
__global__ void k_convw_all(const float* __restrict__ gat_w,
                            const float* __restrict__ lin2_w,
                            const float* __restrict__ lin3_w) {
    int idx = blockIdx.x * blockDim.x + threadIdx.x;
    const int DD = D * D, DHD = D * DHID;
    if (idx < 2 * DD) {
        int l = idx / DD, i = idx - l * DD;
        int k = i / D, n = i - k * D;
        float v = gat_w[l * DD + i];
        __half h = __float2half(v);
        g_wxh[l * DD + n * D + k] = h;
        g_wxl[l * DD + n * D + k] = __float2half(v - __half2float(h));
        return;
    }
    idx -= 2 * DD;
    if (idx < 2 * DHD) {
        int l = idx / DHD, i = idx - l * DHD;
        int k = i / DHID, n = i - k * DHID;
        g_w2h[l * DHD + n * D + k] = __float2half(lin2_w[l * DHD + i]);
        return;
    }
    idx -= 2 * DHD;
    if (idx < 2 * DHD) {
        int l = idx / DHD, i = idx - l * DHD;
        int k = i / D, n = i - k * D;
        g_w3h[l * DHD + n * DHID + k] = __float2half(lin3_w[l * DHD + i]);
    }
}

#define LDK 40
#define TILEE (128 * LDK)
#define SPITCH 132

// ---------------- A-resident fp16 GEMM (K<=128); optional fused attdot tail ----------------
__global__ void __launch_bounds__(256) k_hgemm_ares(
        const __half* __restrict__ A, const __half* __restrict__ Bh,
        const __half* __restrict__ Bl, const float* __restrict__ bias,
        __half* __restrict__ C,
        const float* __restrict__ att_s, const float* __restrict__ att_d,
        int M, int Nc, int K, int relu, int nloop) {
    extern __shared__ __half smh[];
    const int nchA = K / 32;
    const int terms = Bl ? 2 : 1;
    int tid = threadIdx.x, lane = tid & 31, wid = tid >> 5;
    int wm = wid & 3, wn = wid >> 2;
    int row0 = blockIdx.x * 128;
    int g = lane >> 2, t4 = lane & 3;

    if (att_s && blockIdx.x == 0 && tid < D) {
        g_sum[tid] = 0.f;
        g_sumsq[tid] = 0.f;
    }

    int a_row = lane & 15;
    int a_koff = (lane >> 4) << 3;
    int b_nloc = (lane & 7) + ((lane & 16) ? 8 : 0);
    int b_koff = (lane & 8) ? 8 : 0;

    for (int ch = 0; ch < nchA; ch++) {
        __half* sbase = smh + ch * TILEE;
        #pragma unroll
        for (int it = 0; it < 2; it++) {
            int id = it * 256 + tid;
            int m = id >> 2, ko = (id & 3) << 3;
            int gm = row0 + m;
            int sz = 16;
            if (gm >= M) { gm = 0; sz = 0; }
            cpasync16(sm32(sbase + m * LDK + ko), A + (size_t)gm * K + ch * 32 + ko, sz);
        }
    }
    cpcommit();

    auto prefB = [&](int q, int st) {
        int colq = (q / nchA) * 128;
        int kk = (q % nchA) * 32;
        for (int term = 0; term < terms; term++) {
            const __half* gp = (term == 0) ? Bh : Bl;
            __half* sbase = smh + (nchA + st * terms + term) * TILEE;
            #pragma unroll
            for (int it = 0; it < 2; it++) {
                int id = it * 256 + tid;
                int m = id >> 2, ko = (id & 3) << 3;
                cpasync16(sm32(sbase + m * LDK + ko),
                          gp + (size_t)(colq + m) * K + kk + ko, 16);
            }
        }
        cpcommit();
    };

    float acc[2][8][4];
    #pragma unroll
    for (int i = 0; i < 2; i++)
        #pragma unroll
        for (int j = 0; j < 8; j++)
            #pragma unroll
            for (int q = 0; q < 4; q++) acc[i][j][q] = 0.f;

    const int nq = nloop * nchA;
    prefB(0, 0);
    for (int q = 0; q < nq; q++) {
        int st = q & 1;
        if (q + 1 < nq) { prefB(q + 1, st ^ 1); cpwait<1>(); }
        else cpwait<0>();
        __syncthreads();
        const __half* sA  = smh + (q % nchA) * TILEE;
        const __half* sBh = smh + (nchA + st * terms + 0) * TILEE;
        const __half* sBl = smh + (nchA + st * terms + 1) * TILEE;
        #pragma unroll
        for (int ks = 0; ks < 2; ks++) {
            int c = ks * 16;
            uint32_t ar[2][4];
            #pragma unroll
            for (int tm = 0; tm < 2; tm++) {
                int r = wm * 32 + tm * 16 + a_row;
                ldsm4(ar[tm], sm32(&sA[r * LDK + c + a_koff]));
            }
            uint32_t bh[4][4];
            #pragma unroll
            for (int qq = 0; qq < 4; qq++) {
                int n = wn * 64 + qq * 16 + b_nloc;
                ldsm4(bh[qq], sm32(&sBh[n * LDK + c + b_koff]));
            }
            #pragma unroll
            for (int qq = 0; qq < 4; qq++)
                #pragma unroll
                for (int sub = 0; sub < 2; sub++)
                    #pragma unroll
                    for (int tm = 0; tm < 2; tm++)
                        mma16816h(acc[tm][qq * 2 + sub], ar[tm], &bh[qq][sub * 2]);
            if (Bl) {
                uint32_t bl[4][4];
                #pragma unroll
                for (int qq = 0; qq < 4; qq++) {
                    int n = wn * 64 + qq * 16 + b_nloc;
                    ldsm4(bl[qq], sm32(&sBl[n * LDK + c + b_koff]));
                }
                #pragma unroll
                for (int qq = 0; qq < 4; qq++)
                    #pragma unroll
                    for (int sub = 0; sub < 2; sub++)
                        #pragma unroll
                        for (int tm = 0; tm < 2; tm++)
                            mma16816h(acc[tm][qq * 2 + sub], ar[tm], &bl[qq][sub * 2]);
            }
        }
        __syncthreads();
        if ((q % nchA) == nchA - 1) {
            int col0 = (q / nchA) * 128;
            __half* stage = smh;  // A-chunk region idle after last chunk's ldsm (post-sync)
            #pragma unroll
            for (int tm = 0; tm < 2; tm++)
                #pragma unroll
                for (int tn = 0; tn < 8; tn++) {
                    int r = row0 + wm * 32 + tm * 16 + g;
                    int n = col0 + wn * 64 + tn * 8 + 2 * t4;
                    #pragma unroll
                    for (int hf = 0; hf < 2; hf++) {
                        int m = r + hf * 8;
                        if (m >= M) continue;
                        float v0 = acc[tm][tn][hf * 2];
                        float v1 = acc[tm][tn][hf * 2 + 1];
                        if (bias) { v0 += bias[n]; v1 += bias[n + 1]; }
                        if (relu) { v0 = fmaxf(v0, 0.f); v1 = fmaxf(v1, 0.f); }
                        __half2 hv2 = __floats2half2_rn(v0, v1);
                        *(__half2*)&C[(size_t)m * Nc + n] = hv2;
                        if (att_s)
                            *(__half2*)&stage[(m - row0) * SPITCH + n] = hv2;
                        acc[tm][tn][hf * 2] = 0.f;
                        acc[tm][tn][hf * 2 + 1] = 0.f;
                    }
                }
        }
    }

    // fused attdot tail (xl only): read tile from smem staging
    if (att_s) {
        __syncthreads();
        const __half* stage = smh;
        for (int task = tid; task < 128 * HH; task += 256) {
            int r = task >> 3, h = task & 7;
            int gn = row0 + r;
            if (gn >= M) continue;
            const __half2* xr = (const __half2*)&stage[r * SPITCH + h * DVC];
            float s = 0.f, d = 0.f;
            #pragma unroll
            for (int c = 0; c < DVC / 2; c++) {
                float2 v = __half22float2(xr[c]);
                s += v.x * att_s[h * DVC + 2 * c] + v.y * att_s[h * DVC + 2 * c + 1];
                d += v.x * att_d[h * DVC + 2 * c] + v.y * att_d[h * DVC + 2 * c + 1];
            }
            float2 sp; sp.x = s; sp.y = __expf(s);
            float2 dp; dp.x = d; dp.y = __expf(d);
            g_asf[gn * HH + h] = sp;
            g_adf[gn * HH + h] = dp;
        }
    }
}

// ---------------- streaming fp16 GEMM (lin3, K=512), 3-stage ----------------
__global__ void __launch_bounds__(256) k_hgemm(
        const __half* __restrict__ A, const __half* __restrict__ Bh,
        const float* __restrict__ bias, const float* __restrict__ resf,
        float* __restrict__ Cf, int M, int Nc, int K, int zerobn) {
    extern __shared__ __half smh[];
    int tid = threadIdx.x, lane = tid & 31, wid = tid >> 5;
    int wm = wid & 3, wn = wid >> 2;
    int row0 = blockIdx.x * 128, col0 = blockIdx.y * 128;
    int g = lane >> 2, t4 = lane & 3;

    if (zerobn && blockIdx.x == 0 && blockIdx.y == 0 && tid < D) {
        g_sum[tid] = 0.f;
        g_sumsq[tid] = 0.f;
    }

    int a_row = lane & 15;
    int a_koff = (lane >> 4) << 3;
    int b_nloc = (lane & 7) + ((lane & 16) ? 8 : 0);
    int b_koff = (lane & 8) ? 8 : 0;

    float acc[2][8][4];
    #pragma unroll
    for (int i = 0; i < 2; i++)
        #pragma unroll
        for (int j = 0; j < 8; j++)
            #pragma unroll
            for (int q = 0; q < 4; q++) acc[i][j][q] = 0.f;

    const int nch = K / 32;

    auto prefetch = [&](int ch, int st) {
        int kk = ch * 32;
        for (int tile = 0; tile < 2; tile++) {
            const __half* gp = tile == 0 ? A : Bh;
            bool isA = tile == 0;
            __half* sbase = smh + (st * 2 + tile) * TILEE;
            #pragma unroll
            for (int it = 0; it < 2; it++) {
                int id = it * 256 + tid;
                int m = id >> 2, ko = (id & 3) << 3;
                int gm = (isA ? row0 : col0) + m;
                int sz = 16;
                if (isA && gm >= M) { gm = 0; sz = 0; }
                cpasync16(sm32(sbase + m * LDK + ko), gp + (size_t)gm * K + kk + ko, sz);
            }
        }
        cpcommit();
    };

    prefetch(0, 0);
    if (nch > 1) prefetch(1, 1);
    for (int ch = 0; ch < nch; ch++) {
        int st = ch % 3;
        if (ch + 2 < nch) { prefetch(ch + 2, (ch + 2) % 3); cpwait<2>(); }
        else if (ch + 1 < nch) cpwait<1>();
        else cpwait<0>();
        __syncthreads();
        const __half* sA  = smh + (st * 2 + 0) * TILEE;
        const __half* sBh = smh + (st * 2 + 1) * TILEE;
        #pragma unroll
        for (int ks = 0; ks < 2; ks++) {
            int c = ks * 16;
            uint32_t ar[2][4];
            #pragma unroll
            for (int tm = 0; tm < 2; tm++) {
                int r = wm * 32 + tm * 16 + a_row;
                ldsm4(ar[tm], sm32(&sA[r * LDK + c + a_koff]));
            }
            uint32_t bh[4][4];
            #pragma unroll
            for (int q = 0; q < 4; q++) {
                int n = wn * 64 + q * 16 + b_nloc;
                ldsm4(bh[q], sm32(&sBh[n * LDK + c + b_koff]));
            }
            #pragma unroll
            for (int q = 0; q < 4; q++)
                #pragma unroll
                for (int sub = 0; sub < 2; sub++)
                    #pragma unroll
                    for (int tm = 0; tm < 2; tm++)
                        mma16816h(acc[tm][q * 2 + sub], ar[tm], &bh[q][sub * 2]);
        }
        __syncthreads();
    }

    #pragma unroll
    for (int tm = 0; tm < 2; tm++)
        #pragma unroll
        for (int tn = 0; tn < 8; tn++) {
            int r = row0 + wm * 32 + tm * 16 + g;
            int n = col0 + wn * 64 + tn * 8 + 2 * t4;
            #pragma unroll
            for (int hf = 0; hf < 2; hf++) {
                int m = r + hf * 8;
                if (m >= M) continue;
                float v0 = acc[tm][tn][hf * 2] + bias[n];
                float v1 = acc[tm][tn][hf * 2 + 1] + bias[n + 1];
                const float2 rv = *(const float2*)&resf[(size_t)m * Nc + n];
                v0 += rv.x; v1 += rv.y;
                float2 o; o.x = v0; o.y = v1;
                *(float2*)&Cf[(size_t)m * Nc + n] = o;
            }
        }
}

// ---------------- GAT aggregate with inline edge weights ----------------
__global__ void k_gat(const float* __restrict__ lin1w) {
    int n = blockIdx.x;
    int t = threadIdx.x;
    int hh = t >> 4;
    int s = g_off[n], e = g_off[n + 1];
    float2 Bv = g_adf[n * HH + hh];   // (ad, exp(ad)) — node-constant

    float sum = 0.f, acc = 0.f;
    for (int p = s; p < e; p++) {
        int j = g_csr[p];
        float2 Av = g_asf[j * HH + hh];
        float v = Av.x + Bv.x;
        float w = (v > 0.f) ? Av.y * Bv.y : __expf(NEG * v);
        sum += w;
        acc += w * __half2float(g_xlh[j * D + t]);
    }
    acc /= sum;

    __shared__ float sm[D];
    __shared__ float gs[DVC];
    sm[t] = acc;
    __syncthreads();
    if (t < DVC) {
        float g = 0.f;
        #pragma unroll
        for (int h2 = 0; h2 < HH; h2++) g += sm[h2 * DVC + t];
        gs[t] = g;
    }
    __syncthreads();
    float hv = 0.f;
    #pragma unroll
    for (int c = 0; c < DVC; c++) hv += gs[c] * lin1w[c * D + t];
    g_tmp[n * D + t] = g_h[n * D + t] + hv;
}

// ---------------- BatchNorm ----------------
__global__ void k_bnstats(const float* __restrict__ z) {
    int t = threadIdx.x;
    float s = 0.f, q = 0.f;
    for (int n = blockIdx.x; n < NN; n += gridDim.x) {
        float v = z[n * D + t];
        s += v;
        q += v * v;
    }
    atomicAdd(&g_sum[t], s);
    atomicAdd(&g_sumsq[t], q);
}

__global__ void k_bnapply1(const float* __restrict__ z, const float* __restrict__ g,
                           const float* __restrict__ b, float* __restrict__ h1f) {
    int i = blockIdx.x * blockDim.x + threadIdx.x;
    if (i >= NN * D) return;
    int d = i & 127;
    const float invn = 1.f / (float)NN;
    float mu = g_sum[d] * invn;
    float var = g_sumsq[d] * invn - mu * mu;
    float v = g[d] * (z[i] - mu) * rsqrtf(var + BNEPS) + b[d];
    g_h116[i] = __float2half(v);
    h1f[i] = v;
}

__global__ void k_bnapply2(const float* __restrict__ z, const float* __restrict__ g,
                           const float* __restrict__ b, float* __restrict__ out,
                           __half* __restrict__ oh, __half* __restrict__ yh) {
    int i = blockIdx.x * blockDim.x + threadIdx.x;
    if (i >= NN * D) return;
    int d = i & 127;
    const float invn = 1.f / (float)NN;
    float mu = g_sum[d] * invn;
    float var = g_sumsq[d] * invn - mu * mu;
    float v = g[d] * (z[i] - mu) * rsqrtf(var + BNEPS) + b[d];
    out[i] = v;
    if (oh) oh[i] = __float2half(v);
    if (yh) yh[i] = __float2half(g_dinv[i >> 7] * v);
}

// ---------------- APPNP ----------------
__global__ void __launch_bounds__(256) k_appnp_h(const __half* __restrict__ yin,
                                                 __half* __restrict__ yout,
                                                 const float* __restrict__ J,
                                                 float* __restrict__ outp) {
    int w = (blockIdx.x * 256 + threadIdx.x) >> 5;
    if (w >= NN) return;
    int lane = threadIdx.x & 31;
    int n = w;
    int s = g_off[n], e = g_off[n + 1];
    const uint2* y2 = (const uint2*)yin;
    float4 acc = make_float4(0.f, 0.f, 0.f, 0.f);
    int p = s;
    #pragma unroll 1
    for (; p + 8 <= e; p += 8) {
        int j[8];
        #pragma unroll
        for (int q = 0; q < 8; q++) j[q] = g_csr[p + q];
        uint2 u[8];
        #pragma unroll
        for (int q = 0; q < 8; q++) u[q] = y2[(size_t)j[q] * 32 + lane];
        #pragma unroll
        for (int q = 0; q < 8; q++) {
            float2 a = __half22float2(*(__half2*)&u[q].x);
            float2 b = __half22float2(*(__half2*)&u[q].y);
            acc.x += a.x; acc.y += a.y; acc.z += b.x; acc.w += b.y;
        }
    }
    if (p + 4 <= e) {
        int j[4];
        #pragma unroll
        for (int q = 0; q < 4; q++) j[q] = g_csr[p + q];
        uint2 u[4];
        #pragma unroll
        for (int q = 0; q < 4; q++) u[q] = y2[(size_t)j[q] * 32 + lane];
        #pragma unroll
        for (int q = 0; q < 4; q++) {
            float2 a = __half22float2(*(__half2*)&u[q].x);
            float2 b = __half22float2(*(__half2*)&u[q].y);
            acc.x += a.x; acc.y += a.y; acc.z += b.x; acc.w += b.y;
        }
        p += 4;
    }
    for (; p < e; p++) {
        int j = g_csr[p];
        uint2 u = y2[(size_t)j * 32 + lane];
        float2 a = __half22float2(*(__half2*)&u.x);
        float2 b = __half22float2(*(__half2*)&u.y);
        acc.x += a.x; acc.y += a.y; acc.z += b.x; acc.w += b.y;
    }
    float di = g_dinv[n];
    float sc = 0.9f * di;
    float4 h0 = ((const float4*)g_h)[(size_t)n * 32 + lane];
    float4 hv;
    hv.x = sc * acc.x + 0.1f * h0.x;
    hv.y = sc * acc.y + 0.1f * h0.y;
    hv.z = sc * acc.z + 0.1f * h0.z;
    hv.w = sc * acc.w + 0.1f * h0.w;
    if (outp) {
        size_t base = (size_t)n * (D + 1) + 4 * lane;
        outp[base + 0] = hv.x;
        outp[base + 1] = hv.y;
        outp[base + 2] = hv.z;
        outp[base + 3] = hv.w;
        if (lane == 0) outp[(size_t)n * (D + 1) + D] = J[n];
    } else {
        uint2 o;
        *(__half2*)&o.x = __floats2half2_rn(di * hv.x, di * hv.y);
        *(__half2*)&o.y = __floats2half2_rn(di * hv.z, di * hv.w);
        ((uint2*)yout)[(size_t)n * 32 + lane] = o;
    }
}

// ---------------- orchestration ----------------
extern "C" void kernel_launch(void* const* d_in, const int* in_sizes, int n_in,
                              void* d_out, int out_size) {
    const float* x      = (const float*)d_in[0];
    const float* J      = (const float*)d_in[1];
    const int*   ei     = (const int*)d_in[2];
    const float* lin0_w = (const float*)d_in[3];
    const float* lin0_b = (const float*)d_in[4];
    const float* gat_w  = (const float*)d_in[5];
    const float* att_src= (const float*)d_in[6];
    const float* att_dst= (const float*)d_in[7];
    const float* lin1_w = (const float*)d_in[8];
    const float* bn1_g  = (const float*)d_in[9];
    const float* bn1_b  = (const float*)d_in[10];
    const float* lin2_w = (const float*)d_in[11];
    const float* lin2_b = (const float*)d_in[12];
    const float* lin3_w = (const float*)d_in[13];
    const float* lin3_b = (const float*)d_in[14];
    const float* bn2_g  = (const float*)d_in[15];
    const float* bn2_b  = (const float*)d_in[16];
    float* out = (float*)d_out;

    float *ph, *ptmp;
    cudaGetSymbolAddress((void**)&ph, g_h);
    cudaGetSymbolAddress((void**)&ptmp, g_tmp);
    __half *ph16, *pxlh, *pya, *pyb, *ph116, *phid16;
    __half *pwxh, *pwxl, *pw2h, *pw3h;
    cudaGetSymbolAddress((void**)&ph16, g_h16);
    cudaGetSymbolAddress((void**)&pxlh, g_xlh);
    cudaGetSymbolAddress((void**)&pya, g_ya);
    cudaGetSymbolAddress((void**)&pyb, g_yb);
    cudaGetSymbolAddress((void**)&ph116, g_h116);
    cudaGetSymbolAddress((void**)&phid16, g_hid16);
    cudaGetSymbolAddress((void**)&pwxh, g_wxh);
    cudaGetSymbolAddress((void**)&pwxl, g_wxl);
    cudaGetSymbolAddress((void**)&pw2h, g_w2h);
    cudaGetSymbolAddress((void**)&pw3h, g_w3h);

    static bool attrset = false;
    const int GSMA = (4 + 4) * TILEE * (int)sizeof(__half);  // 81920 (ares, 2 terms)
    const int GSMA1 = (4 + 2) * TILEE * (int)sizeof(__half); // 61440 (ares, 1 term)
    const int GSMS = 3 * 2 * TILEE * (int)sizeof(__half);    // 61440 (streaming 3-stage)
    if (!attrset) {
        cudaFuncSetAttribute(k_hgemm_ares, cudaFuncAttributeMaxDynamicSharedMemorySize, GSMA);
        cudaFuncSetAttribute(k_hgemm, cudaFuncAttributeMaxDynamicSharedMemorySize, GSMS);
        attrset = true;
    }

    const int MB = (NN + 127) / 128;  // 391
    const int DD = D * D, DHD = D * DHID;
    const int CONVW_TOT = 2 * DD + 4 * DHD;

    // slots 1-4 arranged so profiled launch #4 = xl GEMM (+ fused attdot)
    k_lin0<<<(NN * D + 255) / 256, 256>>>(x, J, lin0_w, lin0_b);      // also zeroes g_cnt
    k_convw_all<<<(CONVW_TOT + 255) / 256, 256>>>(gat_w, lin2_w, lin3_w);
    k_count<<<(EE + 255) / 256, 256>>>(ei);
    k_hgemm_ares<<<MB, 256, GSMA>>>(ph16, pwxh, pwxl, nullptr, pxlh,
                                    att_src, att_dst, NN, D, D, 0, 1);

    k_scan<<<1, 1024>>>();
    k_fill<<<(ET + 255) / 256, 256>>>(ei);

    for (int l = 0; l < 2; l++) {
        if (l == 1) {
            k_hgemm_ares<<<MB, 256, GSMA>>>(ph16, pwxh + DD, pwxl + DD, nullptr, pxlh,
                                            att_src + HH * DVC, att_dst + HH * DVC,
                                            NN, D, D, 0, 1);
        }
        k_gat<<<NN, 128>>>(lin1_w + (size_t)l * DVC * D);
        k_bnstats<<<512, 128>>>(ptmp);
        k_bnapply1<<<(NN * D + 255) / 256, 256>>>(ptmp, bn1_g + l * D, bn1_b + l * D, ptmp);
        // hidden = relu(h1 @ lin2 + b2): A-resident, 4 column blocks in-kernel
        k_hgemm_ares<<<MB, 256, GSMA1>>>(ph116, pw2h + (size_t)l * DHD, nullptr,
                                         lin2_b + l * DHID, phid16,
                                         nullptr, nullptr, NN, DHID, D, 1, 4);
        // h2pre = hidden @ lin3 + b3 + h1 (in-place fp32) + BN2 zero
        k_hgemm<<<dim3(MB, 1), 256, GSMS>>>(phid16, pw3h + (size_t)l * DHD,
                                            lin3_b + l * D, ptmp, ptmp,
                                            NN, D, DHID, 1);
        k_bnstats<<<512, 128>>>(ptmp);
        if (l == 0)
            k_bnapply2<<<(NN * D + 255) / 256, 256>>>(ptmp, bn2_g + l * D, bn2_b + l * D,
                                                      ph, ph16, nullptr);
        else
            k_bnapply2<<<(NN * D + 255) / 256, 256>>>(ptmp, bn2_g + l * D, bn2_b + l * D,
                                                      ph, nullptr, pya);
    }

    for (int k = 0; k < 10; k++) {
        const __half* yi = (k & 1) ? pyb : pya;
        __half* yo = (k & 1) ? pya : pyb;
        if (k < 9)
            k_appnp_h<<<(NN * 32 + 255) / 256, 256>>>(yi, yo, nullptr, nullptr);
        else
            k_appnp_h<<<(NN * 32 + 255) / 256, 256>>>(yi, nullptr, J, out);
    }
    (void)in_sizes; (void)n_in; (void)out_size;
}

// round 15
// speedup vs baseline: 1.0652x; 1.0652x over previous
#include <cuda_runtime.h>
#include <cuda_fp16.h>
#include <cstdint>

#define NN 50000
#define EE 800000
#define ET (EE + NN)
#define D 128
#define HH 8
#define DVC 16
#define DHID 512
#define NEG 0.2f
#define BNEPS 1e-5f

// ---------------- scratch ----------------
__device__ float g_h[NN * D];
__device__ float g_tmp[NN * D];      // z1 -> h1(f32) -> h2pre (aliased, per-thread RAW safe)
__device__ float2 g_asf[NN * HH];    // (a_src, exp(a_src))
__device__ float2 g_adf[NN * HH];    // (a_dst, exp(a_dst))
__device__ __half g_wh[ET * HH];     // edge softmax numerators (fp16)
__device__ float g_dinv[NN];
__device__ float g_sum[D];
__device__ float g_sumsq[D];
__device__ float g_sum2[D];
__device__ float g_sumsq2[D];
__device__ int g_cnt[NN];
__device__ int g_off[NN + 1];
__device__ int g_cur[NN];
__device__ int g_csr[ET];
__device__ int g_dste[ET];
__device__ __half g_h16[NN * D];             // h fp16 (xl GEMM A)
__device__ __half g_h116[NN * D];            // h1 fp16 (lin2 A)
__device__ __half g_hid16[NN * DHID];        // hidden fp16 (lin3 A)
// per-layer preconverted weights (transposed)
__device__ __half g_wxh[2 * D * D], g_wxl[2 * D * D];
__device__ __half g_w2h[2 * DHID * D];
__device__ __half g_w3h[2 * D * DHID];
__device__ __half g_xlh[NN * D];
__device__ __half g_ya[NN * D], g_yb[NN * D];

// ---------------- PTX helpers ----------------
__device__ __forceinline__ uint32_t sm32(const void* p) {
    uint32_t a;
    asm("{ .reg .u64 t; cvta.to.shared.u64 t, %1; cvt.u32.u64 %0, t; }" : "=r"(a) : "l"(p));
    return a;
}
__device__ __forceinline__ void cpasync16(uint32_t dst, const void* src, int srcsize) {
    asm volatile("cp.async.ca.shared.global [%0], [%1], 16, %2;"
                 :: "r"(dst), "l"(src), "r"(srcsize));
}
__device__ __forceinline__ void cpcommit() {
    asm volatile("cp.async.commit_group;" ::: "memory");
}
template <int N>
__device__ __forceinline__ void cpwait() {
    asm volatile("cp.async.wait_group %0;" :: "n"(N) : "memory");
}
__device__ __forceinline__ void ldsm4(uint32_t* r, uint32_t addr) {
    asm volatile("ldmatrix.sync.aligned.m8n8.x4.shared.b16 {%0,%1,%2,%3}, [%4];"
                 : "=r"(r[0]), "=r"(r[1]), "=r"(r[2]), "=r"(r[3]) : "r"(addr));
}
__device__ __forceinline__ void mma16816h(float* c, const uint32_t* a, const uint32_t* b) {
    asm volatile(
        "mma.sync.aligned.m16n8k16.row.col.f32.f16.f16.f32 "
        "{%0,%1,%2,%3}, {%4,%5,%6,%7}, {%8,%9}, {%0,%1,%2,%3};"
        : "+f"(c[0]), "+f"(c[1]), "+f"(c[2]), "+f"(c[3])
        : "r"(a[0]), "r"(a[1]), "r"(a[2]), "r"(a[3]), "r"(b[0]), "r"(b[1]));
}

// ---------------- CSR construction ----------------
__global__ void k_count(const int* __restrict__ ei) {
    int e = blockIdx.x * blockDim.x + threadIdx.x;
    if (e < EE) atomicAdd(&g_cnt[ei[EE + e]], 1);
}

__global__ void k_scan() {
    __shared__ int warp_sums[32];
    __shared__ int s_carry;
    int t = threadIdx.x;
    int lane = t & 31, wid = t >> 5;
    if (t == 0) { s_carry = 0; g_off[0] = 0; }
    __syncthreads();
    for (int base = 0; base < NN; base += 1024) {
        int i = base + t;
        int v = (i < NN) ? (g_cnt[i] + 1) : 0;
        int x = v;
        #pragma unroll
        for (int d = 1; d < 32; d <<= 1) {
            int y = __shfl_up_sync(0xFFFFFFFFu, x, d);
            if (lane >= d) x += y;
        }
        if (lane == 31) warp_sums[wid] = x;
        __syncthreads();
        if (wid == 0) {
            int w = warp_sums[lane];
            #pragma unroll
            for (int d = 1; d < 32; d <<= 1) {
                int y = __shfl_up_sync(0xFFFFFFFFu, w, d);
                if (lane >= d) w += y;
            }
            warp_sums[lane] = w;
        }
        __syncthreads();
        int incl = x + (wid > 0 ? warp_sums[wid - 1] : 0) + s_carry;
        if (i < NN) g_off[i + 1] = incl;
        __syncthreads();
        if (t == 1023) s_carry = incl;
        __syncthreads();
    }
    for (int i = t; i < NN; i += 1024) {
        int o0 = g_off[i], o1 = g_off[i + 1];
        g_cur[i] = o0;
        g_dinv[i] = rsqrtf((float)(o1 - o0));
    }
}

__global__ void k_fill(const int* __restrict__ ei) {
    int idx = blockIdx.x * blockDim.x + threadIdx.x;
    if (idx >= ET) return;
    int s, d;
    if (idx < EE) { s = ei[idx]; d = ei[EE + idx]; }
    else { s = idx - EE; d = s; }
    int pos = atomicAdd(&g_cur[d], 1);
    g_csr[pos] = s;
    g_dste[pos] = d;
}

// ---------------- lin0 (+ zero cnt) ----------------
__global__ void k_lin0(const float* __restrict__ x, const float* __restrict__ J,
                       const float* __restrict__ w, const float* __restrict__ b) {
    int i = blockIdx.x * blockDim.x + threadIdx.x;
    if (i < NN) g_cnt[i] = 0;
    if (i >= NN * D) return;
    int n = i >> 7, d = i & 127;
    float v = x[n * 2] * w[d] + x[n * 2 + 1] * w[D + d] + J[n] * w[2 * D + d] + b[d];
    g_h[i] = v;
    g_h16[i] = __float2half(v);
}

// ---------------- all weights preconvert + transpose (one kernel) ----------------
__global__ void k_convw_all(const float* __restrict__ gat_w,
                            const float* __restrict__ lin2_w,
                            const float* __restrict__ lin3_w) {
    int idx = blockIdx.x * blockDim.x + threadIdx.x;
    const int DD = D * D, DHD = D * DHID;
    if (idx < 2 * DD) {
        int l = idx / DD, i = idx - l * DD;
        int k = i / D, n = i - k * D;
        float v = gat_w[l * DD + i];
        __half h = __float2half(v);
        g_wxh[l * DD + n * D + k] = h;
        g_wxl[l * DD + n * D + k] = __float2half(v - __half2float(h));
        return;
    }
    idx -= 2 * DD;
    if (idx < 2 * DHD) {
        int l = idx / DHD, i = idx - l * DHD;
        int k = i / DHID, n = i - k * DHID;
        g_w2h[l * DHD + n * D + k] = __float2half(lin2_w[l * DHD + i]);
        return;
    }
    idx -= 2 * DHD;
    if (idx < 2 * DHD) {
        int l = idx / DHD, i = idx - l * DHD;
        int k = i / D, n = i - k * D;
        g_w3h[l * DHD + n * DHID + k] = __float2half(lin3_w[l * DHD + i]);
    }
}

#define LDK 40
#define TILEE (128 * LDK)
#define SPITCH 132

// ---------------- A-resident fp16 GEMM (K<=128); optional fused attdot tail ----------------
__global__ void __launch_bounds__(256) k_hgemm_ares(
        const __half* __restrict__ A, const __half* __restrict__ Bh,
        const __half* __restrict__ Bl, const float* __restrict__ bias,
        __half* __restrict__ C,
        const float* __restrict__ att_s, const float* __restrict__ att_d,
        int M, int Nc, int K, int relu, int nloop) {
    extern __shared__ __half smh[];
    const int nchA = K / 32;
    const int terms = Bl ? 2 : 1;
    int tid = threadIdx.x, lane = tid & 31, wid = tid >> 5;
    int wm = wid & 3, wn = wid >> 2;
    int row0 = blockIdx.x * 128;
    int g = lane >> 2, t4 = lane & 3;

    if (att_s && blockIdx.x == 0 && tid < D) {
        g_sum[tid] = 0.f;
        g_sumsq[tid] = 0.f;
    }

    int a_row = lane & 15;
    int a_koff = (lane >> 4) << 3;
    int b_nloc = (lane & 7) + ((lane & 16) ? 8 : 0);
    int b_koff = (lane & 8) ? 8 : 0;

    for (int ch = 0; ch < nchA; ch++) {
        __half* sbase = smh + ch * TILEE;
        #pragma unroll
        for (int it = 0; it < 2; it++) {
            int id = it * 256 + tid;
            int m = id >> 2, ko = (id & 3) << 3;
            int gm = row0 + m;
            int sz = 16;
            if (gm >= M) { gm = 0; sz = 0; }
            cpasync16(sm32(sbase + m * LDK + ko), A + (size_t)gm * K + ch * 32 + ko, sz);
        }
    }
    cpcommit();

    auto prefB = [&](int q, int st) {
        int colq = (q / nchA) * 128;
        int kk = (q % nchA) * 32;
        for (int term = 0; term < terms; term++) {
            const __half* gp = (term == 0) ? Bh : Bl;
            __half* sbase = smh + (nchA + st * terms + term) * TILEE;
            #pragma unroll
            for (int it = 0; it < 2; it++) {
                int id = it * 256 + tid;
                int m = id >> 2, ko = (id & 3) << 3;
                cpasync16(sm32(sbase + m * LDK + ko),
                          gp + (size_t)(colq + m) * K + kk + ko, 16);
            }
        }
        cpcommit();
    };

    float acc[2][8][4];
    #pragma unroll
    for (int i = 0; i < 2; i++)
        #pragma unroll
        for (int j = 0; j < 8; j++)
            #pragma unroll
            for (int q = 0; q < 4; q++) acc[i][j][q] = 0.f;

    const int nq = nloop * nchA;
    prefB(0, 0);
    for (int q = 0; q < nq; q++) {
        int st = q & 1;
        if (q + 1 < nq) { prefB(q + 1, st ^ 1); cpwait<1>(); }
        else cpwait<0>();
        __syncthreads();
        const __half* sA  = smh + (q % nchA) * TILEE;
        const __half* sBh = smh + (nchA + st * terms + 0) * TILEE;
        const __half* sBl = smh + (nchA + st * terms + 1) * TILEE;
        #pragma unroll
        for (int ks = 0; ks < 2; ks++) {
            int c = ks * 16;
            uint32_t ar[2][4];
            #pragma unroll
            for (int tm = 0; tm < 2; tm++) {
                int r = wm * 32 + tm * 16 + a_row;
                ldsm4(ar[tm], sm32(&sA[r * LDK + c + a_koff]));
            }
            uint32_t bh[4][4];
            #pragma unroll
            for (int qq = 0; qq < 4; qq++) {
                int n = wn * 64 + qq * 16 + b_nloc;
                ldsm4(bh[qq], sm32(&sBh[n * LDK + c + b_koff]));
            }
            #pragma unroll
            for (int qq = 0; qq < 4; qq++)
                #pragma unroll
                for (int sub = 0; sub < 2; sub++)
                    #pragma unroll
                    for (int tm = 0; tm < 2; tm++)
                        mma16816h(acc[tm][qq * 2 + sub], ar[tm], &bh[qq][sub * 2]);
            if (Bl) {
                uint32_t bl[4][4];
                #pragma unroll
                for (int qq = 0; qq < 4; qq++) {
                    int n = wn * 64 + qq * 16 + b_nloc;
                    ldsm4(bl[qq], sm32(&sBl[n * LDK + c + b_koff]));
                }
                #pragma unroll
                for (int qq = 0; qq < 4; qq++)
                    #pragma unroll
                    for (int sub = 0; sub < 2; sub++)
                        #pragma unroll
                        for (int tm = 0; tm < 2; tm++)
                            mma16816h(acc[tm][qq * 2 + sub], ar[tm], &bl[qq][sub * 2]);
            }
        }
        __syncthreads();
        if ((q % nchA) == nchA - 1) {
            int col0 = (q / nchA) * 128;
            __half* stage = smh;  // A-chunk region idle after last chunk's ldsm (post-sync)
            #pragma unroll
            for (int tm = 0; tm < 2; tm++)
                #pragma unroll
                for (int tn = 0; tn < 8; tn++) {
                    int r = row0 + wm * 32 + tm * 16 + g;
                    int n = col0 + wn * 64 + tn * 8 + 2 * t4;
                    #pragma unroll
                    for (int hf = 0; hf < 2; hf++) {
                        int m = r + hf * 8;
                        if (m >= M) continue;
                        float v0 = acc[tm][tn][hf * 2];
                        float v1 = acc[tm][tn][hf * 2 + 1];
                        if (bias) { v0 += bias[n]; v1 += bias[n + 1]; }
                        if (relu) { v0 = fmaxf(v0, 0.f); v1 = fmaxf(v1, 0.f); }
                        __half2 hv2 = __floats2half2_rn(v0, v1);
                        *(__half2*)&C[(size_t)m * Nc + n] = hv2;
                        if (att_s)
                            *(__half2*)&stage[(m - row0) * SPITCH + n] = hv2;
                        acc[tm][tn][hf * 2] = 0.f;
                        acc[tm][tn][hf * 2 + 1] = 0.f;
                    }
                }
        }
    }

    // fused attdot tail (xl only): read tile from smem staging
    if (att_s) {
        __syncthreads();
        const __half* stage = smh;
        for (int task = tid; task < 128 * HH; task += 256) {
            int r = task >> 3, h = task & 7;
            int gn = row0 + r;
            if (gn >= M) continue;
            const __half2* xr = (const __half2*)&stage[r * SPITCH + h * DVC];
            float s = 0.f, d = 0.f;
            #pragma unroll
            for (int c = 0; c < DVC / 2; c++) {
                float2 v = __half22float2(xr[c]);
                s += v.x * att_s[h * DVC + 2 * c] + v.y * att_s[h * DVC + 2 * c + 1];
                d += v.x * att_d[h * DVC + 2 * c] + v.y * att_d[h * DVC + 2 * c + 1];
            }
            float2 sp; sp.x = s; sp.y = __expf(s);
            float2 dp; dp.x = d; dp.y = __expf(d);
            g_asf[gn * HH + h] = sp;
            g_adf[gn * HH + h] = dp;
        }
    }
}

// ---------------- streaming fp16 GEMM (lin3, K=512), 3-stage, fused BN2 stats ----------------
__global__ void __launch_bounds__(256) k_hgemm(
        const __half* __restrict__ A, const __half* __restrict__ Bh,
        const float* __restrict__ bias, const float* __restrict__ resf,
        float* __restrict__ Cf, int M, int Nc, int K) {
    extern __shared__ __half smh[];
    __shared__ float ssum[128], ssq[128];
    int tid = threadIdx.x, lane = tid & 31, wid = tid >> 5;
    int wm = wid & 3, wn = wid >> 2;
    int row0 = blockIdx.x * 128, col0 = blockIdx.y * 128;
    int g = lane >> 2, t4 = lane & 3;

    if (tid < 128) { ssum[tid] = 0.f; ssq[tid] = 0.f; }

    int a_row = lane & 15;
    int a_koff = (lane >> 4) << 3;
    int b_nloc = (lane & 7) + ((lane & 16) ? 8 : 0);
    int b_koff = (lane & 8) ? 8 : 0;

    float acc[2][8][4];
    #pragma unroll
    for (int i = 0; i < 2; i++)
        #pragma unroll
        for (int j = 0; j < 8; j++)
            #pragma unroll
            for (int q = 0; q < 4; q++) acc[i][j][q] = 0.f;

    const int nch = K / 32;

    auto prefetch = [&](int ch, int st) {
        int kk = ch * 32;
        for (int tile = 0; tile < 2; tile++) {
            const __half* gp = tile == 0 ? A : Bh;
            bool isA = tile == 0;
            __half* sbase = smh + (st * 2 + tile) * TILEE;
            #pragma unroll
            for (int it = 0; it < 2; it++) {
                int id = it * 256 + tid;
                int m = id >> 2, ko = (id & 3) << 3;
                int gm = (isA ? row0 : col0) + m;
                int sz = 16;
                if (isA && gm >= M) { gm = 0; sz = 0; }
                cpasync16(sm32(sbase + m * LDK + ko), gp + (size_t)gm * K + kk + ko, sz);
            }
        }
        cpcommit();
    };

    prefetch(0, 0);
    if (nch > 1) prefetch(1, 1);
    for (int ch = 0; ch < nch; ch++) {
        int st = ch % 3;
        if (ch + 2 < nch) { prefetch(ch + 2, (ch + 2) % 3); cpwait<2>(); }
        else if (ch + 1 < nch) cpwait<1>();
        else cpwait<0>();
        __syncthreads();
        const __half* sA  = smh + (st * 2 + 0) * TILEE;
        const __half* sBh = smh + (st * 2 + 1) * TILEE;
        #pragma unroll
        for (int ks = 0; ks < 2; ks++) {
            int c = ks * 16;
            uint32_t ar[2][4];
            #pragma unroll
            for (int tm = 0; tm < 2; tm++) {
                int r = wm * 32 + tm * 16 + a_row;
                ldsm4(ar[tm], sm32(&sA[r * LDK + c + a_koff]));
            }
            uint32_t bh[4][4];
            #pragma unroll
            for (int q = 0; q < 4; q++) {
                int n = wn * 64 + q * 16 + b_nloc;
                ldsm4(bh[q], sm32(&sBh[n * LDK + c + b_koff]));
            }
            #pragma unroll
            for (int q = 0; q < 4; q++)
                #pragma unroll
                for (int sub = 0; sub < 2; sub++)
                    #pragma unroll
                    for (int tm = 0; tm < 2; tm++)
                        mma16816h(acc[tm][q * 2 + sub], ar[tm], &bh[q][sub * 2]);
        }
        __syncthreads();
    }

    // epilogue with fused per-column stats (sum over g lanes via butterflies)
    #pragma unroll
    for (int tn = 0; tn < 8; tn++) {
        int n = col0 + wn * 64 + tn * 8 + 2 * t4;
        float s0 = 0.f, s1 = 0.f, q0 = 0.f, q1 = 0.f;
        #pragma unroll
        for (int tm = 0; tm < 2; tm++)
            #pragma unroll
            for (int hf = 0; hf < 2; hf++) {
                int m = row0 + wm * 32 + tm * 16 + g + hf * 8;
                if (m >= M) continue;
                float v0 = acc[tm][tn][hf * 2] + bias[n];
                float v1 = acc[tm][tn][hf * 2 + 1] + bias[n + 1];
                const float2 rv = *(const float2*)&resf[(size_t)m * Nc + n];
                v0 += rv.x; v1 += rv.y;
                float2 o; o.x = v0; o.y = v1;
                *(float2*)&Cf[(size_t)m * Nc + n] = o;
                s0 += v0; s1 += v1;
                q0 += v0 * v0; q1 += v1 * v1;
            }
        #pragma unroll
        for (int mk = 4; mk <= 16; mk <<= 1) {
            s0 += __shfl_xor_sync(0xFFFFFFFFu, s0, mk);
            s1 += __shfl_xor_sync(0xFFFFFFFFu, s1, mk);
            q0 += __shfl_xor_sync(0xFFFFFFFFu, q0, mk);
            q1 += __shfl_xor_sync(0xFFFFFFFFu, q1, mk);
        }
        if (lane < 4) {
            int cl = wn * 64 + tn * 8 + 2 * t4;
            atomicAdd(&ssum[cl], s0);
            atomicAdd(&ssum[cl + 1], s1);
            atomicAdd(&ssq[cl], q0);
            atomicAdd(&ssq[cl + 1], q1);
        }
    }
    __syncthreads();
    if (tid < 128) {
        atomicAdd(&g_sum2[col0 + tid], ssum[tid]);
        atomicAdd(&g_sumsq2[col0 + tid], ssq[tid]);
    }
}

// ---------------- edge weights: factored exp, fp16 store ----------------
__global__ void k_ew() {
    int idx = blockIdx.x * blockDim.x + threadIdx.x;
    if (idx >= ET * HH) return;
    int p = idx >> 3, h = idx & 7;
    int s = g_csr[p], d = g_dste[p];
    float2 A = g_asf[s * HH + h];
    float2 B = g_adf[d * HH + h];
    float v = A.x + B.x;
    float w = (v > 0.f) ? A.y * B.y : __expf(NEG * v);
    g_wh[idx] = __float2half(w);
}

// ---------------- GAT aggregate ----------------
__global__ void k_gat(const float* __restrict__ lin1w) {
    int n = blockIdx.x;
    int t = threadIdx.x;
    int hh = t >> 4;
    int s = g_off[n], e = g_off[n + 1];

    float sum = 0.f, acc = 0.f;
    for (int p = s; p < e; p++) {
        int j = g_csr[p];
        float w = __half2float(g_wh[p * HH + hh]);
        sum += w;
        acc += w * __half2float(g_xlh[j * D + t]);
    }
    acc /= sum;

    __shared__ float sm[D];
    __shared__ float gs[DVC];
    sm[t] = acc;
    __syncthreads();
    if (t < DVC) {
        float g = 0.f;
        #pragma unroll
        for (int h2 = 0; h2 < HH; h2++) g += sm[h2 * DVC + t];
        gs[t] = g;
    }
    __syncthreads();
    float hv = 0.f;
    #pragma unroll
    for (int c = 0; c < DVC; c++) hv += gs[c] * lin1w[c * D + t];
    g_tmp[n * D + t] = g_h[n * D + t] + hv;
}

// ---------------- BatchNorm ----------------
__global__ void k_bnstats(const float* __restrict__ z) {
    int t = threadIdx.x;
    float s = 0.f, q = 0.f;
    for (int n = blockIdx.x; n < NN; n += gridDim.x) {
        float v = z[n * D + t];
        s += v;
        q += v * v;
    }
    atomicAdd(&g_sum[t], s);
    atomicAdd(&g_sumsq[t], q);
}

// BN1 apply; also zeroes BN2 stat buffers (race-free: before lin3 launch)
__global__ void k_bnapply1(const float* __restrict__ z, const float* __restrict__ g,
                           const float* __restrict__ b, float* __restrict__ h1f) {
    int i = blockIdx.x * blockDim.x + threadIdx.x;
    if (i < D) { g_sum2[i] = 0.f; g_sumsq2[i] = 0.f; }
    if (i >= NN * D) return;
    int d = i & 127;
    const float invn = 1.f / (float)NN;
    float mu = g_sum[d] * invn;
    float var = g_sumsq[d] * invn - mu * mu;
    float v = g[d] * (z[i] - mu) * rsqrtf(var + BNEPS) + b[d];
    g_h116[i] = __float2half(v);
    h1f[i] = v;
}

// BN2 apply (stats from lin3 epilogue in g_sum2)
__global__ void k_bnapply2(const float* __restrict__ z, const float* __restrict__ g,
                           const float* __restrict__ b, float* __restrict__ out,
                           __half* __restrict__ oh, __half* __restrict__ yh) {
    int i = blockIdx.x * blockDim.x + threadIdx.x;
    if (i >= NN * D) return;
    int d = i & 127;
    const float invn = 1.f / (float)NN;
    float mu = g_sum2[d] * invn;
    float var = g_sumsq2[d] * invn - mu * mu;
    float v = g[d] * (z[i] - mu) * rsqrtf(var + BNEPS) + b[d];
    out[i] = v;
    if (oh) oh[i] = __float2half(v);
    if (yh) yh[i] = __float2half(g_dinv[i >> 7] * v);
}

// ---------------- APPNP ----------------
__global__ void __launch_bounds__(256) k_appnp_h(const __half* __restrict__ yin,
                                                 __half* __restrict__ yout,
                                                 const float* __restrict__ J,
                                                 float* __restrict__ outp) {
    int w = (blockIdx.x * 256 + threadIdx.x) >> 5;
    if (w >= NN) return;
    int lane = threadIdx.x & 31;
    int n = w;
    int s = g_off[n], e = g_off[n + 1];
    const uint2* y2 = (const uint2*)yin;
    float4 acc = make_float4(0.f, 0.f, 0.f, 0.f);
    int p = s;
    #pragma unroll 1
    for (; p + 8 <= e; p += 8) {
        int j[8];
        #pragma unroll
        for (int q = 0; q < 8; q++) j[q] = g_csr[p + q];
        uint2 u[8];
        #pragma unroll
        for (int q = 0; q < 8; q++) u[q] = y2[(size_t)j[q] * 32 + lane];
        #pragma unroll
        for (int q = 0; q < 8; q++) {
            float2 a = __half22float2(*(__half2*)&u[q].x);
            float2 b = __half22float2(*(__half2*)&u[q].y);
            acc.x += a.x; acc.y += a.y; acc.z += b.x; acc.w += b.y;
        }
    }
    if (p + 4 <= e) {
        int j[4];
        #pragma unroll
        for (int q = 0; q < 4; q++) j[q] = g_csr[p + q];
        uint2 u[4];
        #pragma unroll
        for (int q = 0; q < 4; q++) u[q] = y2[(size_t)j[q] * 32 + lane];
        #pragma unroll
        for (int q = 0; q < 4; q++) {
            float2 a = __half22float2(*(__half2*)&u[q].x);
            float2 b = __half22float2(*(__half2*)&u[q].y);
            acc.x += a.x; acc.y += a.y; acc.z += b.x; acc.w += b.y;
        }
        p += 4;
    }
    for (; p < e; p++) {
        int j = g_csr[p];
        uint2 u = y2[(size_t)j * 32 + lane];
        float2 a = __half22float2(*(__half2*)&u.x);
        float2 b = __half22float2(*(__half2*)&u.y);
        acc.x += a.x; acc.y += a.y; acc.z += b.x; acc.w += b.y;
    }
    float di = g_dinv[n];
    float sc = 0.9f * di;
    float4 h0 = ((const float4*)g_h)[(size_t)n * 32 + lane];
    float4 hv;
    hv.x = sc * acc.x + 0.1f * h0.x;
    hv.y = sc * acc.y + 0.1f * h0.y;
    hv.z = sc * acc.z + 0.1f * h0.z;
    hv.w = sc * acc.w + 0.1f * h0.w;
    if (outp) {
        size_t base = (size_t)n * (D + 1) + 4 * lane;
        outp[base + 0] = hv.x;
        outp[base + 1] = hv.y;
        outp[base + 2] = hv.z;
        outp[base + 3] = hv.w;
        if (lane == 0) outp[(size_t)n * (D + 1) + D] = J[n];
    } else {
        uint2 o;
        *(__half2*)&o.x = __floats2half2_rn(di * hv.x, di * hv.y);
        *(__half2*)&o.y = __floats2half2_rn(di * hv.z, di * hv.w);
        ((uint2*)yout)[(size_t)n * 32 + lane] = o;
    }
}

// ---------------- orchestration ----------------
extern "C" void kernel_launch(void* const* d_in, const int* in_sizes, int n_in,
                              void* d_out, int out_size) {
    const float* x      = (const float*)d_in[0];
    const float* J      = (const float*)d_in[1];
    const int*   ei     = (const int*)d_in[2];
    const float* lin0_w = (const float*)d_in[3];
    const float* lin0_b = (const float*)d_in[4];
    const float* gat_w  = (const float*)d_in[5];
    const float* att_src= (const float*)d_in[6];
    const float* att_dst= (const float*)d_in[7];
    const float* lin1_w = (const float*)d_in[8];
    const float* bn1_g  = (const float*)d_in[9];
    const float* bn1_b  = (const float*)d_in[10];
    const float* lin2_w = (const float*)d_in[11];
    const float* lin2_b = (const float*)d_in[12];
    const float* lin3_w = (const float*)d_in[13];
    const float* lin3_b = (const float*)d_in[14];
    const float* bn2_g  = (const float*)d_in[15];
    const float* bn2_b  = (const float*)d_in[16];
    float* out = (float*)d_out;

    float *ph, *ptmp;
    cudaGetSymbolAddress((void**)&ph, g_h);
    cudaGetSymbolAddress((void**)&ptmp, g_tmp);
    __half *ph16, *pxlh, *pya, *pyb, *ph116, *phid16;
    __half *pwxh, *pwxl, *pw2h, *pw3h;
    cudaGetSymbolAddress((void**)&ph16, g_h16);
    cudaGetSymbolAddress((void**)&pxlh, g_xlh);
    cudaGetSymbolAddress((void**)&pya, g_ya);
    cudaGetSymbolAddress((void**)&pyb, g_yb);
    cudaGetSymbolAddress((void**)&ph116, g_h116);
    cudaGetSymbolAddress((void**)&phid16, g_hid16);
    cudaGetSymbolAddress((void**)&pwxh, g_wxh);
    cudaGetSymbolAddress((void**)&pwxl, g_wxl);
    cudaGetSymbolAddress((void**)&pw2h, g_w2h);
    cudaGetSymbolAddress((void**)&pw3h, g_w3h);

    static bool attrset = false;
    const int GSMA = (4 + 4) * TILEE * (int)sizeof(__half);  // 81920 (ares, 2 terms)
    const int GSMA1 = (4 + 2) * TILEE * (int)sizeof(__half); // 61440 (ares, 1 term)
    const int GSMS = 3 * 2 * TILEE * (int)sizeof(__half);    // 61440 (streaming 3-stage)
    if (!attrset) {
        cudaFuncSetAttribute(k_hgemm_ares, cudaFuncAttributeMaxDynamicSharedMemorySize, GSMA);
        cudaFuncSetAttribute(k_hgemm, cudaFuncAttributeMaxDynamicSharedMemorySize, GSMS);
        attrset = true;
    }

    const int MB = (NN + 127) / 128;  // 391
    const int DD = D * D, DHD = D * DHID;
    const int CONVW_TOT = 2 * DD + 4 * DHD;

    // slots 1-4 arranged so profiled launch #4 = xl GEMM (+ fused attdot)
    k_lin0<<<(NN * D + 255) / 256, 256>>>(x, J, lin0_w, lin0_b);      // also zeroes g_cnt
    k_convw_all<<<(CONVW_TOT + 255) / 256, 256>>>(gat_w, lin2_w, lin3_w);
    k_count<<<(EE + 255) / 256, 256>>>(ei);
    k_hgemm_ares<<<MB, 256, GSMA>>>(ph16, pwxh, pwxl, nullptr, pxlh,
                                    att_src, att_dst, NN, D, D, 0, 1);

    k_scan<<<1, 1024>>>();
    k_fill<<<(ET + 255) / 256, 256>>>(ei);

    for (int l = 0; l < 2; l++) {
        if (l == 1) {
            k_hgemm_ares<<<MB, 256, GSMA>>>(ph16, pwxh + DD, pwxl + DD, nullptr, pxlh,
                                            att_src + HH * DVC, att_dst + HH * DVC,
                                            NN, D, D, 0, 1);
        }
        k_ew<<<(ET * HH + 255) / 256, 256>>>();
        k_gat<<<NN, 128>>>(lin1_w + (size_t)l * DVC * D);
        k_bnstats<<<512, 128>>>(ptmp);
        k_bnapply1<<<(NN * D + 255) / 256, 256>>>(ptmp, bn1_g + l * D, bn1_b + l * D, ptmp);
        // hidden = relu(h1 @ lin2 + b2): A-resident, 4 column blocks in-kernel
        k_hgemm_ares<<<MB, 256, GSMA1>>>(ph116, pw2h + (size_t)l * DHD, nullptr,
                                         lin2_b + l * DHID, phid16,
                                         nullptr, nullptr, NN, DHID, D, 1, 4);
        // h2pre = hidden @ lin3 + b3 + h1 (in-place fp32), BN2 stats fused
        k_hgemm<<<dim3(MB, 1), 256, GSMS>>>(phid16, pw3h + (size_t)l * DHD,
                                            lin3_b + l * D, ptmp, ptmp,
                                            NN, D, DHID);
        if (l == 0)
            k_bnapply2<<<(NN * D + 255) / 256, 256>>>(ptmp, bn2_g + l * D, bn2_b + l * D,
                                                      ph, ph16, nullptr);
        else
            k_bnapply2<<<(NN * D + 255) / 256, 256>>>(ptmp, bn2_g + l * D, bn2_b + l * D,
                                                      ph, nullptr, pya);
    }

    for (int k = 0; k < 10; k++) {
        const __half* yi = (k & 1) ? pyb : pya;
        __half* yo = (k & 1) ? pya : pyb;
        if (k < 9)
            k_appnp_h<<<(NN * 32 + 255) / 256, 256>>>(yi, yo, nullptr, nullptr);
        else
            k_appnp_h<<<(NN * 32 + 255) / 256, 256>>>(yi, nullptr, J, out);
    }
    (void)in_sizes; (void)n_in; (void)out_size;
}

// round 16
// speedup vs baseline: 1.1153x; 1.0470x over previous
#include <cuda_runtime.h>
#include <cuda_fp16.h>
#include <cstdint>

#define NN 50000
#define EE 800000
#define ET (EE + NN)
#define D 128
#define HH 8
#define DVC 16
#define DHID 512
#define NEG 0.2f
#define BNEPS 1e-5f
#define SCB 256
#define SCNB ((NN + SCB - 1) / SCB)   // 196

// ---------------- scratch ----------------
__device__ float g_h[NN * D];
__device__ float g_tmp[NN * D];
__device__ float2 g_asf[NN * HH];
__device__ float2 g_adf[NN * HH];
__device__ __half g_wh[ET * HH];
__device__ float g_dinv[NN];
__device__ float g_sum[D];
__device__ float g_sumsq[D];
__device__ float g_sum2[D];
__device__ float g_sumsq2[D];
__device__ int g_cnt[NN];
__device__ int g_off[NN + 1];
__device__ int g_cur[NN];
__device__ int g_csr[ET];
__device__ int g_dste[ET];
__device__ int g_btot[SCNB];
__device__ int g_bbase[SCNB];
__device__ __half g_h16[NN * D];
__device__ __half g_h116[NN * D];
__device__ __half g_hid16[NN * DHID];
__device__ __half g_wxh[2 * D * D], g_wxl[2 * D * D];
__device__ __half g_w2h[2 * DHID * D];
__device__ __half g_w3h[2 * D * DHID];
__device__ __half g_xlh[NN * D];
__device__ __half g_ya[NN * D], g_yb[NN * D];

// ---------------- PTX helpers ----------------
__device__ __forceinline__ uint32_t sm32(const void* p) {
    uint32_t a;
    asm("{ .reg .u64 t; cvta.to.shared.u64 t, %1; cvt.u32.u64 %0, t; }" : "=r"(a) : "l"(p));
    return a;
}
__device__ __forceinline__ void cpasync16(uint32_t dst, const void* src, int srcsize) {
    asm volatile("cp.async.ca.shared.global [%0], [%1], 16, %2;"
                 :: "r"(dst), "l"(src), "r"(srcsize));
}
__device__ __forceinline__ void cpcommit() {
    asm volatile("cp.async.commit_group;" ::: "memory");
}
template <int N>
__device__ __forceinline__ void cpwait() {
    asm volatile("cp.async.wait_group %0;" :: "n"(N) : "memory");
}
__device__ __forceinline__ void ldsm4(uint32_t* r, uint32_t addr) {
    asm volatile("ldmatrix.sync.aligned.m8n8.x4.shared.b16 {%0,%1,%2,%3}, [%4];"
                 : "=r"(r[0]), "=r"(r[1]), "=r"(r[2]), "=r"(r[3]) : "r"(addr));
}
__device__ __forceinline__ void mma16816h(float* c, const uint32_t* a, const uint32_t* b) {
    asm volatile(
        "mma.sync.aligned.m16n8k16.row.col.f32.f16.f16.f32 "
        "{%0,%1,%2,%3}, {%4,%5,%6,%7}, {%8,%9}, {%0,%1,%2,%3};"
        : "+f"(c[0]), "+f"(c[1]), "+f"(c[2]), "+f"(c[3])
        : "r"(a[0]), "r"(a[1]), "r"(a[2]), "r"(a[3]), "r"(b[0]), "r"(b[1]));
}

// ---------------- CSR construction ----------------
__global__ void k_count(const int* __restrict__ ei) {
    int e = blockIdx.x * blockDim.x + threadIdx.x;
    if (e < EE) atomicAdd(&g_cnt[ei[EE + e]], 1);
}

// phase 1: per-block local inclusive scan of (cnt+1); store local prefix + block total
__global__ void k_scan1() {
    __shared__ int wsum[8];
    int b = blockIdx.x, t = threadIdx.x;
    int lane = t & 31, wid = t >> 5;
    int i = b * SCB + t;
    int v = (i < NN) ? (g_cnt[i] + 1) : 0;
    int x = v;
    #pragma unroll
    for (int d = 1; d < 32; d <<= 1) {
        int y = __shfl_up_sync(0xFFFFFFFFu, x, d);
        if (lane >= d) x += y;
    }
    if (lane == 31) wsum[wid] = x;
    __syncthreads();
    if (wid == 0 && lane < 8) {
        int w = wsum[lane];
        #pragma unroll
        for (int d = 1; d < 8; d <<= 1) {
            int y = __shfl_up_sync(0xFFu, w, d);
            if (lane >= d) w += y;
        }
        wsum[lane] = w;
    }
    __syncthreads();
    int incl = x + (wid > 0 ? wsum[wid - 1] : 0);
    if (i < NN) g_off[i + 1] = incl;   // local inclusive; base added in phase 3
    if (t == SCB - 1) g_btot[b] = incl;
}

// phase 2: scan the 196 block totals (one small block)
__global__ void k_scan2() {
    __shared__ int sh[SCNB];
    int t = threadIdx.x;
    for (int i = t; i < SCNB; i += blockDim.x) sh[i] = g_btot[i];
    __syncthreads();
    if (t == 0) {
        int run = 0;
        g_off[0] = 0;
        for (int i = 0; i < SCNB; i++) {
            g_bbase[i] = run;
            run += sh[i];
        }
    }
}

// phase 3: add base, derive cur/dinv (deg = cnt+1 directly)
__global__ void k_scan3() {
    int b = blockIdx.x, t = threadIdx.x;
    int i = b * SCB + t;
    if (i >= NN) return;
    int base = g_bbase[b];
    int incl = g_off[i + 1] + base;
    g_off[i + 1] = incl;
    int deg = g_cnt[i] + 1;
    g_cur[i] = incl - deg;
    g_dinv[i] = rsqrtf((float)deg);
}

__global__ void k_fill(const int* __restrict__ ei) {
    int idx = blockIdx.x * blockDim.x + threadIdx.x;
    if (idx >= ET) return;
    int s, d;
    if (idx < EE) { s = ei[idx]; d = ei[EE + idx]; }
    else { s = idx - EE; d = s; }
    int pos = atomicAdd(&g_cur[d], 1);
    g_csr[pos] = s;
    g_dste[pos] = d;
}

// g_cur was advanced by k_fill; restore to segment starts for any reuse (not needed, but cheap)
// (not used — removed)

// ---------------- lin0 (+ zero cnt) ----------------
__global__ void k_lin0(const float* __restrict__ x, const float* __restrict__ J,
                       const float* __restrict__ w, const float* __restrict__ b) {
    int i = blockIdx.x * blockDim.x + threadIdx.x;
    if (i < NN) g_cnt[i] = 0;
    if (i >= NN * D) return;
    int n = i >> 7, d = i & 127;
    float v = x[n * 2] * w[d] + x[n * 2 + 1] * w[D + d] + J[n] * w[2 * D + d] + b[d];
    g_h[i] = v;
    g_h16[i] = __float2half(v);
}

// ---------------- all weights preconvert + transpose ----------------
__global__ void k_convw_all(const float* __restrict__ gat_w,
                            const float* __restrict__ lin2_w,
                            const float* __restrict__ lin3_w) {
    int idx = blockIdx.x * blockDim.x + threadIdx.x;
    const int DD = D * D, DHD = D * DHID;
    if (idx < 2 * DD) {
        int l = idx / DD, i = idx - l * DD;
        int k = i / D, n = i - k * D;
        float v = gat_w[l * DD + i];
        __half h = __float2half(v);
        g_wxh[l * DD + n * D + k] = h;
        g_wxl[l * DD + n * D + k] = __float2half(v - __half2float(h));
        return;
    }
    idx -= 2 * DD;
    if (idx < 2 * DHD) {
        int l = idx / DHD, i = idx - l * DHD;
        int k = i / DHID, n = i - k * DHID;
        g_w2h[l * DHD + n * D + k] = __float2half(lin2_w[l * DHD + i]);
        return;
    }
    idx -= 2 * DHD;
    if (idx < 2 * DHD) {
        int l = idx / DHD, i = idx - l * DHD;
        int k = i / D, n = i - k * D;
        g_w3h[l * DHD + n * DHID + k] = __float2half(lin3_w[l * DHD + i]);
    }
}

#define LDK 40
#define TILEE (128 * LDK)
#define SPITCH 132

// ---------------- A-resident fp16 GEMM (K<=128); optional fused attdot tail ----------------
__global__ void __launch_bounds__(256) k_hgemm_ares(
        const __half* __restrict__ A, const __half* __restrict__ Bh,
        const __half* __restrict__ Bl, const float* __restrict__ bias,
        __half* __restrict__ C,
        const float* __restrict__ att_s, const float* __restrict__ att_d,
        int M, int Nc, int K, int relu, int nloop) {
    extern __shared__ __half smh[];
    const int nchA = K / 32;
    const int terms = Bl ? 2 : 1;
    int tid = threadIdx.x, lane = tid & 31, wid = tid >> 5;
    int wm = wid & 3, wn = wid >> 2;
    int row0 = blockIdx.x * 128;
    int g = lane >> 2, t4 = lane & 3;

    if (att_s && blockIdx.x == 0 && tid < D) {
        g_sum[tid] = 0.f;
        g_sumsq[tid] = 0.f;
    }

    int a_row = lane & 15;
    int a_koff = (lane >> 4) << 3;
    int b_nloc = (lane & 7) + ((lane & 16) ? 8 : 0);
    int b_koff = (lane & 8) ? 8 : 0;

    for (int ch = 0; ch < nchA; ch++) {
        __half* sbase = smh + ch * TILEE;
        #pragma unroll
        for (int it = 0; it < 2; it++) {
            int id = it * 256 + tid;
            int m = id >> 2, ko = (id & 3) << 3;
            int gm = row0 + m;
            int sz = 16;
            if (gm >= M) { gm = 0; sz = 0; }
            cpasync16(sm32(sbase + m * LDK + ko), A + (size_t)gm * K + ch * 32 + ko, sz);
        }
    }
    cpcommit();

    auto prefB = [&](int q, int st) {
        int colq = (q / nchA) * 128;
        int kk = (q % nchA) * 32;
        for (int term = 0; term < terms; term++) {
            const __half* gp = (term == 0) ? Bh : Bl;
            __half* sbase = smh + (nchA + st * terms + term) * TILEE;
            #pragma unroll
            for (int it = 0; it < 2; it++) {
                int id = it * 256 + tid;
                int m = id >> 2, ko = (id & 3) << 3;
                cpasync16(sm32(sbase + m * LDK + ko),
                          gp + (size_t)(colq + m) * K + kk + ko, 16);
            }
        }
        cpcommit();
    };

    float acc[2][8][4];
    #pragma unroll
    for (int i = 0; i < 2; i++)
        #pragma unroll
        for (int j = 0; j < 8; j++)
            #pragma unroll
            for (int q = 0; q < 4; q++) acc[i][j][q] = 0.f;

    const int nq = nloop * nchA;
    prefB(0, 0);
    for (int q = 0; q < nq; q++) {
        int st = q & 1;
        if (q + 1 < nq) { prefB(q + 1, st ^ 1); cpwait<1>(); }
        else cpwait<0>();
        __syncthreads();
        const __half* sA  = smh + (q % nchA) * TILEE;
        const __half* sBh = smh + (nchA + st * terms + 0) * TILEE;
        const __half* sBl = smh + (nchA + st * terms + 1) * TILEE;
        #pragma unroll
        for (int ks = 0; ks < 2; ks++) {
            int c = ks * 16;
            uint32_t ar[2][4];
            #pragma unroll
            for (int tm = 0; tm < 2; tm++) {
                int r = wm * 32 + tm * 16 + a_row;
                ldsm4(ar[tm], sm32(&sA[r * LDK + c + a_koff]));
            }
            uint32_t bh[4][4];
            #pragma unroll
            for (int qq = 0; qq < 4; qq++) {
                int n = wn * 64 + qq * 16 + b_nloc;
                ldsm4(bh[qq], sm32(&sBh[n * LDK + c + b_koff]));
            }
            #pragma unroll
            for (int qq = 0; qq < 4; qq++)
                #pragma unroll
                for (int sub = 0; sub < 2; sub++)
                    #pragma unroll
                    for (int tm = 0; tm < 2; tm++)
                        mma16816h(acc[tm][qq * 2 + sub], ar[tm], &bh[qq][sub * 2]);
            if (Bl) {
                uint32_t bl[4][4];
                #pragma unroll
                for (int qq = 0; qq < 4; qq++) {
                    int n = wn * 64 + qq * 16 + b_nloc;
                    ldsm4(bl[qq], sm32(&sBl[n * LDK + c + b_koff]));
                }
                #pragma unroll
                for (int qq = 0; qq < 4; qq++)
                    #pragma unroll
                    for (int sub = 0; sub < 2; sub++)
                        #pragma unroll
                        for (int tm = 0; tm < 2; tm++)
                            mma16816h(acc[tm][qq * 2 + sub], ar[tm], &bl[qq][sub * 2]);
            }
        }
        __syncthreads();
        if ((q % nchA) == nchA - 1) {
            int col0 = (q / nchA) * 128;
            __half* stage = smh;
            #pragma unroll
            for (int tm = 0; tm < 2; tm++)
                #pragma unroll
                for (int tn = 0; tn < 8; tn++) {
                    int r = row0 + wm * 32 + tm * 16 + g;
                    int n = col0 + wn * 64 + tn * 8 + 2 * t4;
                    #pragma unroll
                    for (int hf = 0; hf < 2; hf++) {
                        int m = r + hf * 8;
                        if (m >= M) continue;
                        float v0 = acc[tm][tn][hf * 2];
                        float v1 = acc[tm][tn][hf * 2 + 1];
                        if (bias) { v0 += bias[n]; v1 += bias[n + 1]; }
                        if (relu) { v0 = fmaxf(v0, 0.f); v1 = fmaxf(v1, 0.f); }
                        __half2 hv2 = __floats2half2_rn(v0, v1);
                        *(__half2*)&C[(size_t)m * Nc + n] = hv2;
                        if (att_s)
                            *(__half2*)&stage[(m - row0) * SPITCH + n] = hv2;
                        acc[tm][tn][hf * 2] = 0.f;
                        acc[tm][tn][hf * 2 + 1] = 0.f;
                    }
                }
        }
    }

    if (att_s) {
        __syncthreads();
        const __half* stage = smh;
        for (int task = tid; task < 128 * HH; task += 256) {
            int r = task >> 3, h = task & 7;
            int gn = row0 + r;
            if (gn >= M) continue;
            const __half2* xr = (const __half2*)&stage[r * SPITCH + h * DVC];
            float s = 0.f, d = 0.f;
            #pragma unroll
            for (int c = 0; c < DVC / 2; c++) {
                float2 v = __half22float2(xr[c]);
                s += v.x * att_s[h * DVC + 2 * c] + v.y * att_s[h * DVC + 2 * c + 1];
                d += v.x * att_d[h * DVC + 2 * c] + v.y * att_d[h * DVC + 2 * c + 1];
            }
            float2 sp; sp.x = s; sp.y = __expf(s);
            float2 dp; dp.x = d; dp.y = __expf(d);
            g_asf[gn * HH + h] = sp;
            g_adf[gn * HH + h] = dp;
        }
    }
}

// ---------------- streaming fp16 GEMM (lin3, K=512), 3-stage, fused BN2 stats ----------------
__global__ void __launch_bounds__(256) k_hgemm(
        const __half* __restrict__ A, const __half* __restrict__ Bh,
        const float* __restrict__ bias, const float* __restrict__ resf,
        float* __restrict__ Cf, int M, int Nc, int K) {
    extern __shared__ __half smh[];
    __shared__ float ssum[128], ssq[128];
    int tid = threadIdx.x, lane = tid & 31, wid = tid >> 5;
    int wm = wid & 3, wn = wid >> 2;
    int row0 = blockIdx.x * 128, col0 = blockIdx.y * 128;
    int g = lane >> 2, t4 = lane & 3;

    if (tid < 128) { ssum[tid] = 0.f; ssq[tid] = 0.f; }

    int a_row = lane & 15;
    int a_koff = (lane >> 4) << 3;
    int b_nloc = (lane & 7) + ((lane & 16) ? 8 : 0);
    int b_koff = (lane & 8) ? 8 : 0;

    float acc[2][8][4];
    #pragma unroll
    for (int i = 0; i < 2; i++)
        #pragma unroll
        for (int j = 0; j < 8; j++)
            #pragma unroll
            for (int q = 0; q < 4; q++) acc[i][j][q] = 0.f;

    const int nch = K / 32;

    auto prefetch = [&](int ch, int st) {
        int kk = ch * 32;
        for (int tile = 0; tile < 2; tile++) {
            const __half* gp = tile == 0 ? A : Bh;
            bool isA = tile == 0;
            __half* sbase = smh + (st * 2 + tile) * TILEE;
            #pragma unroll
            for (int it = 0; it < 2; it++) {
                int id = it * 256 + tid;
                int m = id >> 2, ko = (id & 3) << 3;
                int gm = (isA ? row0 : col0) + m;
                int sz = 16;
                if (isA && gm >= M) { gm = 0; sz = 0; }
                cpasync16(sm32(sbase + m * LDK + ko), gp + (size_t)gm * K + kk + ko, sz);
            }
        }
        cpcommit();
    };

    prefetch(0, 0);
    if (nch > 1) prefetch(1, 1);
    for (int ch = 0; ch < nch; ch++) {
        int st = ch % 3;
        if (ch + 2 < nch) { prefetch(ch + 2, (ch + 2) % 3); cpwait<2>(); }
        else if (ch + 1 < nch) cpwait<1>();
        else cpwait<0>();
        __syncthreads();
        const __half* sA  = smh + (st * 2 + 0) * TILEE;
        const __half* sBh = smh + (st * 2 + 1) * TILEE;
        #pragma unroll
        for (int ks = 0; ks < 2; ks++) {
            int c = ks * 16;
            uint32_t ar[2][4];
            #pragma unroll
            for (int tm = 0; tm < 2; tm++) {
                int r = wm * 32 + tm * 16 + a_row;
                ldsm4(ar[tm], sm32(&sA[r * LDK + c + a_koff]));
            }
            uint32_t bh[4][4];
            #pragma unroll
            for (int q = 0; q < 4; q++) {
                int n = wn * 64 + q * 16 + b_nloc;
                ldsm4(bh[q], sm32(&sBh[n * LDK + c + b_koff]));
            }
            #pragma unroll
            for (int q = 0; q < 4; q++)
                #pragma unroll
                for (int sub = 0; sub < 2; sub++)
                    #pragma unroll
                    for (int tm = 0; tm < 2; tm++)
                        mma16816h(acc[tm][q * 2 + sub], ar[tm], &bh[q][sub * 2]);
        }
        __syncthreads();
    }

    #pragma unroll
    for (int tn = 0; tn < 8; tn++) {
        int n = col0 + wn * 64 + tn * 8 + 2 * t4;
        float s0 = 0.f, s1 = 0.f, q0 = 0.f, q1 = 0.f;
        #pragma unroll
        for (int tm = 0; tm < 2; tm++)
            #pragma unroll
            for (int hf = 0; hf < 2; hf++) {
                int m = row0 + wm * 32 + tm * 16 + g + hf * 8;
                if (m >= M) continue;
                float v0 = acc[tm][tn][hf * 2] + bias[n];
                float v1 = acc[tm][tn][hf * 2 + 1] + bias[n + 1];
                const float2 rv = *(const float2*)&resf[(size_t)m * Nc + n];
                v0 += rv.x; v1 += rv.y;
                float2 o; o.x = v0; o.y = v1;
                *(float2*)&Cf[(size_t)m * Nc + n] = o;
                s0 += v0; s1 += v1;
                q0 += v0 * v0; q1 += v1 * v1;
            }
        #pragma unroll
        for (int mk = 4; mk <= 16; mk <<= 1) {
            s0 += __shfl_xor_sync(0xFFFFFFFFu, s0, mk);
            s1 += __shfl_xor_sync(0xFFFFFFFFu, s1, mk);
            q0 += __shfl_xor_sync(0xFFFFFFFFu, q0, mk);
            q1 += __shfl_xor_sync(0xFFFFFFFFu, q1, mk);
        }
        if (lane < 4) {
            int cl = wn * 64 + tn * 8 + 2 * t4;
            atomicAdd(&ssum[cl], s0);
            atomicAdd(&ssum[cl + 1], s1);
            atomicAdd(&ssq[cl], q0);
            atomicAdd(&ssq[cl + 1], q1);
        }
    }
    __syncthreads();
    if (tid < 128) {
        atomicAdd(&g_sum2[col0 + tid], ssum[tid]);
        atomicAdd(&g_sumsq2[col0 + tid], ssq[tid]);
    }
}

// ---------------- edge weights ----------------
__global__ void k_ew() {
    int idx = blockIdx.x * blockDim.x + threadIdx.x;
    if (idx >= ET * HH) return;
    int p = idx >> 3, h = idx & 7;
    int s = g_csr[p], d = g_dste[p];
    float2 A = g_asf[s * HH + h];
    float2 B = g_adf[d * HH + h];
    float v = A.x + B.x;
    float w = (v > 0.f) ? A.y * B.y : __expf(NEG * v);
    g_wh[idx] = __float2half(w);
}

// ---------------- GAT aggregate ----------------
__global__ void k_gat(const float* __restrict__ lin1w) {
    int n = blockIdx.x;
    int t = threadIdx.x;
    int hh = t >> 4;
    int s = g_off[n], e = g_off[n + 1];

    float sum = 0.f, acc = 0.f;
    for (int p = s; p < e; p++) {
        int j = g_csr[p];
        float w = __half2float(g_wh[p * HH + hh]);
        sum += w;
        acc += w * __half2float(g_xlh[j * D + t]);
    }
    acc /= sum;

    __shared__ float sm[D];
    __shared__ float gs[DVC];
    sm[t] = acc;
    __syncthreads();
    if (t < DVC) {
        float g = 0.f;
        #pragma unroll
        for (int h2 = 0; h2 < HH; h2++) g += sm[h2 * DVC + t];
        gs[t] = g;
    }
    __syncthreads();
    float hv = 0.f;
    #pragma unroll
    for (int c = 0; c < DVC; c++) hv += gs[c] * lin1w[c * D + t];
    g_tmp[n * D + t] = g_h[n * D + t] + hv;
}

// ---------------- BatchNorm ----------------
__global__ void k_bnstats(const float* __restrict__ z) {
    int t = threadIdx.x;
    float s = 0.f, q = 0.f;
    for (int n = blockIdx.x; n < NN; n += gridDim.x) {
        float v = z[n * D + t];
        s += v;
        q += v * v;
    }
    atomicAdd(&g_sum[t], s);
    atomicAdd(&g_sumsq[t], q);
}

__global__ void k_bnapply1(const float* __restrict__ z, const float* __restrict__ g,
                           const float* __restrict__ b, float* __restrict__ h1f) {
    int i = blockIdx.x * blockDim.x + threadIdx.x;
    if (i < D) { g_sum2[i] = 0.f; g_sumsq2[i] = 0.f; }
    if (i >= NN * D) return;
    int d = i & 127;
    const float invn = 1.f / (float)NN;
    float mu = g_sum[d] * invn;
    float var = g_sumsq[d] * invn - mu * mu;
    float v = g[d] * (z[i] - mu) * rsqrtf(var + BNEPS) + b[d];
    g_h116[i] = __float2half(v);
    h1f[i] = v;
}

__global__ void k_bnapply2(const float* __restrict__ z, const float* __restrict__ g,
                           const float* __restrict__ b, float* __restrict__ out,
                           __half* __restrict__ oh, __half* __restrict__ yh) {
    int i = blockIdx.x * blockDim.x + threadIdx.x;
    if (i >= NN * D) return;
    int d = i & 127;
    const float invn = 1.f / (float)NN;
    float mu = g_sum2[d] * invn;
    float var = g_sumsq2[d] * invn - mu * mu;
    float v = g[d] * (z[i] - mu) * rsqrtf(var + BNEPS) + b[d];
    out[i] = v;
    if (oh) oh[i] = __float2half(v);
    if (yh) yh[i] = __float2half(g_dinv[i >> 7] * v);
}

// ---------------- APPNP ----------------
__global__ void __launch_bounds__(256) k_appnp_h(const __half* __restrict__ yin,
                                                 __half* __restrict__ yout,
                                                 const float* __restrict__ J,
                                                 float* __restrict__ outp) {
    int w = (blockIdx.x * 256 + threadIdx.x) >> 5;
    if (w >= NN) return;
    int lane = threadIdx.x & 31;
    int n = w;
    int s = g_off[n], e = g_off[n + 1];
    const uint2* y2 = (const uint2*)yin;
    float4 acc = make_float4(0.f, 0.f, 0.f, 0.f);
    int p = s;
    #pragma unroll 1
    for (; p + 8 <= e; p += 8) {
        int j[8];
        #pragma unroll
        for (int q = 0; q < 8; q++) j[q] = g_csr[p + q];
        uint2 u[8];
        #pragma unroll
        for (int q = 0; q < 8; q++) u[q] = y2[(size_t)j[q] * 32 + lane];
        #pragma unroll
        for (int q = 0; q < 8; q++) {
            float2 a = __half22float2(*(__half2*)&u[q].x);
            float2 b = __half22float2(*(__half2*)&u[q].y);
            acc.x += a.x; acc.y += a.y; acc.z += b.x; acc.w += b.y;
        }
    }
    if (p + 4 <= e) {
        int j[4];
        #pragma unroll
        for (int q = 0; q < 4; q++) j[q] = g_csr[p + q];
        uint2 u[4];
        #pragma unroll
        for (int q = 0; q < 4; q++) u[q] = y2[(size_t)j[q] * 32 + lane];
        #pragma unroll
        for (int q = 0; q < 4; q++) {
            float2 a = __half22float2(*(__half2*)&u[q].x);
            float2 b = __half22float2(*(__half2*)&u[q].y);
            acc.x += a.x; acc.y += a.y; acc.z += b.x; acc.w += b.y;
        }
        p += 4;
    }
    for (; p < e; p++) {
        int j = g_csr[p];
        uint2 u = y2[(size_t)j * 32 + lane];
        float2 a = __half22float2(*(__half2*)&u.x);
        float2 b = __half22float2(*(__half2*)&u.y);
        acc.x += a.x; acc.y += a.y; acc.z += b.x; acc.w += b.y;
    }
    float di = g_dinv[n];
    float sc = 0.9f * di;
    float4 h0 = ((const float4*)g_h)[(size_t)n * 32 + lane];
    float4 hv;
    hv.x = sc * acc.x + 0.1f * h0.x;
    hv.y = sc * acc.y + 0.1f * h0.y;
    hv.z = sc * acc.z + 0.1f * h0.z;
    hv.w = sc * acc.w + 0.1f * h0.w;
    if (outp) {
        size_t base = (size_t)n * (D + 1) + 4 * lane;
        outp[base + 0] = hv.x;
        outp[base + 1] = hv.y;
        outp[base + 2] = hv.z;
        outp[base + 3] = hv.w;
        if (lane == 0) outp[(size_t)n * (D + 1) + D] = J[n];
    } else {
        uint2 o;
        *(__half2*)&o.x = __floats2half2_rn(di * hv.x, di * hv.y);
        *(__half2*)&o.y = __floats2half2_rn(di * hv.z, di * hv.w);
        ((uint2*)yout)[(size_t)n * 32 + lane] = o;
    }
}

// ---------------- orchestration ----------------
extern "C" void kernel_launch(void* const* d_in, const int* in_sizes, int n_in,
                              void* d_out, int out_size) {
    const float* x      = (const float*)d_in[0];
    const float* J      = (const float*)d_in[1];
    const int*   ei     = (const int*)d_in[2];
    const float* lin0_w = (const float*)d_in[3];
    const float* lin0_b = (const float*)d_in[4];
    const float* gat_w  = (const float*)d_in[5];
    const float* att_src= (const float*)d_in[6];
    const float* att_dst= (const float*)d_in[7];
    const float* lin1_w = (const float*)d_in[8];
    const float* bn1_g  = (const float*)d_in[9];
    const float* bn1_b  = (const float*)d_in[10];
    const float* lin2_w = (const float*)d_in[11];
    const float* lin2_b = (const float*)d_in[12];
    const float* lin3_w = (const float*)d_in[13];
    const float* lin3_b = (const float*)d_in[14];
    const float* bn2_g  = (const float*)d_in[15];
    const float* bn2_b  = (const float*)d_in[16];
    float* out = (float*)d_out;

    float *ph, *ptmp;
    cudaGetSymbolAddress((void**)&ph, g_h);
    cudaGetSymbolAddress((void**)&ptmp, g_tmp);
    __half *ph16, *pxlh, *pya, *pyb, *ph116, *phid16;
    __half *pwxh, *pwxl, *pw2h, *pw3h;
    cudaGetSymbolAddress((void**)&ph16, g_h16);
    cudaGetSymbolAddress((void**)&pxlh, g_xlh);
    cudaGetSymbolAddress((void**)&pya, g_ya);
    cudaGetSymbolAddress((void**)&pyb, g_yb);
    cudaGetSymbolAddress((void**)&ph116, g_h116);
    cudaGetSymbolAddress((void**)&phid16, g_hid16);
    cudaGetSymbolAddress((void**)&pwxh, g_wxh);
    cudaGetSymbolAddress((void**)&pwxl, g_wxl);
    cudaGetSymbolAddress((void**)&pw2h, g_w2h);
    cudaGetSymbolAddress((void**)&pw3h, g_w3h);

    static bool attrset = false;
    const int GSMA = (4 + 4) * TILEE * (int)sizeof(__half);
    const int GSMA1 = (4 + 2) * TILEE * (int)sizeof(__half);
    const int GSMS = 3 * 2 * TILEE * (int)sizeof(__half);
    if (!attrset) {
        cudaFuncSetAttribute(k_hgemm_ares, cudaFuncAttributeMaxDynamicSharedMemorySize, GSMA);
        cudaFuncSetAttribute(k_hgemm, cudaFuncAttributeMaxDynamicSharedMemorySize, GSMS);
        attrset = true;
    }

    const int MB = (NN + 127) / 128;  // 391
    const int DD = D * D, DHD = D * DHID;
    const int CONVW_TOT = 2 * DD + 4 * DHD;

    // slots 1-4 arranged so profiled launch #4 = xl GEMM (+ fused attdot)
    k_lin0<<<(NN * D + 255) / 256, 256>>>(x, J, lin0_w, lin0_b);      // also zeroes g_cnt
    k_convw_all<<<(CONVW_TOT + 255) / 256, 256>>>(gat_w, lin2_w, lin3_w);
    k_count<<<(EE + 255) / 256, 256>>>(ei);
    k_hgemm_ares<<<MB, 256, GSMA>>>(ph16, pwxh, pwxl, nullptr, pxlh,
                                    att_src, att_dst, NN, D, D, 0, 1);

    k_scan1<<<SCNB, SCB>>>();
    k_scan2<<<1, 256>>>();
    k_scan3<<<SCNB, SCB>>>();
    k_fill<<<(ET + 255) / 256, 256>>>(ei);

    for (int l = 0; l < 2; l++) {
        if (l == 1) {
            k_hgemm_ares<<<MB, 256, GSMA>>>(ph16, pwxh + DD, pwxl + DD, nullptr, pxlh,
                                            att_src + HH * DVC, att_dst + HH * DVC,
                                            NN, D, D, 0, 1);
        }
        k_ew<<<(ET * HH + 255) / 256, 256>>>();
        k_gat<<<NN, 128>>>(lin1_w + (size_t)l * DVC * D);
        k_bnstats<<<512, 128>>>(ptmp);
        k_bnapply1<<<(NN * D + 255) / 256, 256>>>(ptmp, bn1_g + l * D, bn1_b + l * D, ptmp);
        k_hgemm_ares<<<MB, 256, GSMA1>>>(ph116, pw2h + (size_t)l * DHD, nullptr,
                                         lin2_b + l * DHID, phid16,
                                         nullptr, nullptr, NN, DHID, D, 1, 4);
        k_hgemm<<<dim3(MB, 1), 256, GSMS>>>(phid16, pw3h + (size_t)l * DHD,
                                            lin3_b + l * D, ptmp, ptmp,
                                            NN, D, DHID);
        if (l == 0)
            k_bnapply2<<<(NN * D + 255) / 256, 256>>>(ptmp, bn2_g + l * D, bn2_b + l * D,
                                                      ph, ph16, nullptr);
        else
            k_bnapply2<<<(NN * D + 255) / 256, 256>>>(ptmp, bn2_g + l * D, bn2_b + l * D,
                                                      ph, nullptr, pya);
    }

    for (int k = 0; k < 10; k++) {
        const __half* yi = (k & 1) ? pyb : pya;
        __half* yo = (k & 1) ? pya : pyb;
        if (k < 9)
            k_appnp_h<<<(NN * 32 + 255) / 256, 256>>>(yi, yo, nullptr, nullptr);
        else
            k_appnp_h<<<(NN * 32 + 255) / 256, 256>>>(yi, nullptr, J, out);
    }
    (void)in_sizes; (void)n_in; (void)out_size;
}

// round 17
// speedup vs baseline: 1.1602x; 1.0403x over previous
#include <cuda_runtime.h>
#include <cuda_fp16.h>
#include <cstdint>

#define NN 50000
#define EE 800000
#define ET (EE + NN)
#define D 128
#define HH 8
#define DVC 16
#define DHID 512
#define NEG 0.2f
#define BNEPS 1e-5f
#define SCB 256
#define SCNB ((NN + SCB - 1) / SCB)   // 196

// ---------------- scratch ----------------
__device__ float g_h[NN * D];
__device__ float g_tmp[NN * D];
__device__ float2 g_asf[NN * HH];
__device__ float2 g_adf[NN * HH];
__device__ __half g_wh[ET * HH];
__device__ float g_dinv[NN];
__device__ float g_sum[D];
__device__ float g_sumsq[D];
__device__ float g_sum2[D];
__device__ float g_sumsq2[D];
__device__ int g_cnt[NN];
__device__ int g_off[NN + 1];
__device__ int g_cur[NN];
__device__ int g_csr[ET];
__device__ int g_dste[ET];
__device__ int g_btot[SCNB];
__device__ int g_bbase[SCNB];
__device__ __half g_h16[NN * D];
__device__ __half g_h116[NN * D];
__device__ __half g_hid16[NN * DHID];
__device__ __half g_wxh[2 * D * D], g_wxl[2 * D * D];
__device__ __half g_w2h[2 * DHID * D];
__device__ __half g_w3h[2 * D * DHID];
__device__ __half g_xlh[NN * D];
__device__ __half g_ya[NN * D], g_yb[NN * D];

// ---------------- PTX helpers ----------------
__device__ __forceinline__ uint32_t sm32(const void* p) {
    uint32_t a;
    asm("{ .reg .u64 t; cvta.to.shared.u64 t, %1; cvt.u32.u64 %0, t; }" : "=r"(a) : "l"(p));
    return a;
}
__device__ __forceinline__ void cpasync16(uint32_t dst, const void* src, int srcsize) {
    asm volatile("cp.async.ca.shared.global [%0], [%1], 16, %2;"
                 :: "r"(dst), "l"(src), "r"(srcsize));
}
__device__ __forceinline__ void cpcommit() {
    asm volatile("cp.async.commit_group;" ::: "memory");
}
template <int N>
__device__ __forceinline__ void cpwait() {
    asm volatile("cp.async.wait_group %0;" :: "n"(N) : "memory");
}
__device__ __forceinline__ void ldsm4(uint32_t* r, uint32_t addr) {
    asm volatile("ldmatrix.sync.aligned.m8n8.x4.shared.b16 {%0,%1,%2,%3}, [%4];"
                 : "=r"(r[0]), "=r"(r[1]), "=r"(r[2]), "=r"(r[3]) : "r"(addr));
}
__device__ __forceinline__ void mma16816h(float* c, const uint32_t* a, const uint32_t* b) {
    asm volatile(
        "mma.sync.aligned.m16n8k16.row.col.f32.f16.f16.f32 "
        "{%0,%1,%2,%3}, {%4,%5,%6,%7}, {%8,%9}, {%0,%1,%2,%3};"
        : "+f"(c[0]), "+f"(c[1]), "+f"(c[2]), "+f"(c[3])
        : "r"(a[0]), "r"(a[1]), "r"(a[2]), "r"(a[3]), "r"(b[0]), "r"(b[1]));
}

// ---------------- CSR construction ----------------
__global__ void k_count(const int* __restrict__ ei) {
    int e = blockIdx.x * blockDim.x + threadIdx.x;
    if (e < EE) atomicAdd(&g_cnt[ei[EE + e]], 1);
}

__global__ void k_scan1() {
    __shared__ int wsum[8];
    int b = blockIdx.x, t = threadIdx.x;
    int lane = t & 31, wid = t >> 5;
    int i = b * SCB + t;
    int v = (i < NN) ? (g_cnt[i] + 1) : 0;
    int x = v;
    #pragma unroll
    for (int d = 1; d < 32; d <<= 1) {
        int y = __shfl_up_sync(0xFFFFFFFFu, x, d);
        if (lane >= d) x += y;
    }
    if (lane == 31) wsum[wid] = x;
    __syncthreads();
    if (wid == 0 && lane < 8) {
        int w = wsum[lane];
        #pragma unroll
        for (int d = 1; d < 8; d <<= 1) {
            int y = __shfl_up_sync(0xFFu, w, d);
            if (lane >= d) w += y;
        }
        wsum[lane] = w;
    }
    __syncthreads();
    int incl = x + (wid > 0 ? wsum[wid - 1] : 0);
    if (i < NN) g_off[i + 1] = incl;
    if (t == SCB - 1) g_btot[b] = incl;
}

__global__ void k_scan2() {
    __shared__ int sh[SCNB];
    int t = threadIdx.x;
    for (int i = t; i < SCNB; i += blockDim.x) sh[i] = g_btot[i];
    __syncthreads();
    if (t == 0) {
        int run = 0;
        g_off[0] = 0;
        for (int i = 0; i < SCNB; i++) {
            g_bbase[i] = run;
            run += sh[i];
        }
    }
}

__global__ void k_scan3() {
    int b = blockIdx.x, t = threadIdx.x;
    int i = b * SCB + t;
    if (i >= NN) return;
    int base = g_bbase[b];
    int incl = g_off[i + 1] + base;
    g_off[i + 1] = incl;
    int deg = g_cnt[i] + 1;
    g_cur[i] = incl - deg;
    g_dinv[i] = rsqrtf((float)deg);
}

__global__ void k_fill(const int* __restrict__ ei) {
    int idx = blockIdx.x * blockDim.x + threadIdx.x;
    if (idx >= ET) return;
    int s, d;
    if (idx < EE) { s = ei[idx]; d = ei[EE + idx]; }
    else { s = idx - EE; d = s; }
    int pos = atomicAdd(&g_cur[d], 1);
    g_csr[pos] = s;
    g_dste[pos] = d;
}

// ---------------- lin0 (+ zero cnt) ----------------
__global__ void k_lin0(const float* __restrict__ x, const float* __restrict__ J,
                       const float* __restrict__ w, const float* __restrict__ b) {
    int i = blockIdx.x * blockDim.x + threadIdx.x;
    if (i < NN) g_cnt[i] = 0;
    if (i >= NN * D) return;
    int n = i >> 7, d = i & 127;
    float v = x[n * 2] * w[d] + x[n * 2 + 1] * w[D + d] + J[n] * w[2 * D + d] + b[d];
    g_h[i] = v;
    g_h16[i] = __float2half(v);
}

// ---------------- all weights preconvert + transpose ----------------
__global__ void k_convw_all(const float* __restrict__ gat_w,
                            const float* __restrict__ lin2_w,
                            const float* __restrict__ lin3_w) {
    int idx = blockIdx.x * blockDim.x + threadIdx.x;
    const int DD = D * D, DHD = D * DHID;
    if (idx < 2 * DD) {
        int l = idx / DD, i = idx - l * DD;
        int k = i / D, n = i - k * D;
        float v = gat_w[l * DD + i];
        __half h = __float2half(v);
        g_wxh[l * DD + n * D + k] = h;
        g_wxl[l * DD + n * D + k] = __float2half(v - __half2float(h));
        return;
    }
    idx -= 2 * DD;
    if (idx < 2 * DHD) {
        int l = idx / DHD, i = idx - l * DHD;
        int k = i / DHID, n = i - k * DHID;
        g_w2h[l * DHD + n * D + k] = __float2half(lin2_w[l * DHD + i]);
        return;
    }
    idx -= 2 * DHD;
    if (idx < 2 * DHD) {
        int l = idx / DHD, i = idx - l * DHD;
        int k = i / D, n = i - k * D;
        g_w3h[l * DHD + n * DHID + k] = __float2half(lin3_w[l * DHD + i]);
    }
}

#define LDK 40
#define TILEE (128 * LDK)
#define SPITCH 132

// ---------------- A-resident fp16 GEMM (K<=128); optional fused attdot tail ----------------
__global__ void __launch_bounds__(256) k_hgemm_ares(
        const __half* __restrict__ A, const __half* __restrict__ Bh,
        const __half* __restrict__ Bl, const float* __restrict__ bias,
        __half* __restrict__ C,
        const float* __restrict__ att_s, const float* __restrict__ att_d,
        int M, int Nc, int K, int relu, int nloop) {
    extern __shared__ __half smh[];
    const int nchA = K / 32;
    const int terms = Bl ? 2 : 1;
    int tid = threadIdx.x, lane = tid & 31, wid = tid >> 5;
    int wm = wid & 3, wn = wid >> 2;
    int row0 = blockIdx.x * 128;
    int g = lane >> 2, t4 = lane & 3;

    if (att_s && blockIdx.x == 0 && tid < D) {
        g_sum[tid] = 0.f;
        g_sumsq[tid] = 0.f;
    }

    int a_row = lane & 15;
    int a_koff = (lane >> 4) << 3;
    int b_nloc = (lane & 7) + ((lane & 16) ? 8 : 0);
    int b_koff = (lane & 8) ? 8 : 0;

    for (int ch = 0; ch < nchA; ch++) {
        __half* sbase = smh + ch * TILEE;
        #pragma unroll
        for (int it = 0; it < 2; it++) {
            int id = it * 256 + tid;
            int m = id >> 2, ko = (id & 3) << 3;
            int gm = row0 + m;
            int sz = 16;
            if (gm >= M) { gm = 0; sz = 0; }
            cpasync16(sm32(sbase + m * LDK + ko), A + (size_t)gm * K + ch * 32 + ko, sz);
        }
    }
    cpcommit();

    auto prefB = [&](int q, int st) {
        int colq = (q / nchA) * 128;
        int kk = (q % nchA) * 32;
        for (int term = 0; term < terms; term++) {
            const __half* gp = (term == 0) ? Bh : Bl;
            __half* sbase = smh + (nchA + st * terms + term) * TILEE;
            #pragma unroll
            for (int it = 0; it < 2; it++) {
                int id = it * 256 + tid;
                int m = id >> 2, ko = (id & 3) << 3;
                cpasync16(sm32(sbase + m * LDK + ko),
                          gp + (size_t)(colq + m) * K + kk + ko, 16);
            }
        }
        cpcommit();
    };

    float acc[2][8][4];
    #pragma unroll
    for (int i = 0; i < 2; i++)
        #pragma unroll
        for (int j = 0; j < 8; j++)
            #pragma unroll
            for (int q = 0; q < 4; q++) acc[i][j][q] = 0.f;

    const int nq = nloop * nchA;
    prefB(0, 0);
    for (int q = 0; q < nq; q++) {
        int st = q & 1;
        if (q + 1 < nq) { prefB(q + 1, st ^ 1); cpwait<1>(); }
        else cpwait<0>();
        __syncthreads();
        const __half* sA  = smh + (q % nchA) * TILEE;
        const __half* sBh = smh + (nchA + st * terms + 0) * TILEE;
        const __half* sBl = smh + (nchA + st * terms + 1) * TILEE;
        #pragma unroll
        for (int ks = 0; ks < 2; ks++) {
            int c = ks * 16;
            uint32_t ar[2][4];
            #pragma unroll
            for (int tm = 0; tm < 2; tm++) {
                int r = wm * 32 + tm * 16 + a_row;
                ldsm4(ar[tm], sm32(&sA[r * LDK + c + a_koff]));
            }
            uint32_t bh[4][4];
            #pragma unroll
            for (int qq = 0; qq < 4; qq++) {
                int n = wn * 64 + qq * 16 + b_nloc;
                ldsm4(bh[qq], sm32(&sBh[n * LDK + c + b_koff]));
            }
            #pragma unroll
            for (int qq = 0; qq < 4; qq++)
                #pragma unroll
                for (int sub = 0; sub < 2; sub++)
                    #pragma unroll
                    for (int tm = 0; tm < 2; tm++)
                        mma16816h(acc[tm][qq * 2 + sub], ar[tm], &bh[qq][sub * 2]);
            if (Bl) {
                uint32_t bl[4][4];
                #pragma unroll
                for (int qq = 0; qq < 4; qq++) {
                    int n = wn * 64 + qq * 16 + b_nloc;
                    ldsm4(bl[qq], sm32(&sBl[n * LDK + c + b_koff]));
                }
                #pragma unroll
                for (int qq = 0; qq < 4; qq++)
                    #pragma unroll
                    for (int sub = 0; sub < 2; sub++)
                        #pragma unroll
                        for (int tm = 0; tm < 2; tm++)
                            mma16816h(acc[tm][qq * 2 + sub], ar[tm], &bl[qq][sub * 2]);
            }
        }
        __syncthreads();
        if ((q % nchA) == nchA - 1) {
            int col0 = (q / nchA) * 128;
            __half* stage = smh;
            #pragma unroll
            for (int tm = 0; tm < 2; tm++)
                #pragma unroll
                for (int tn = 0; tn < 8; tn++) {
                    int r = row0 + wm * 32 + tm * 16 + g;
                    int n = col0 + wn * 64 + tn * 8 + 2 * t4;
                    #pragma unroll
                    for (int hf = 0; hf < 2; hf++) {
                        int m = r + hf * 8;
                        if (m >= M) continue;
                        float v0 = acc[tm][tn][hf * 2];
                        float v1 = acc[tm][tn][hf * 2 + 1];
                        if (bias) { v0 += bias[n]; v1 += bias[n + 1]; }
                        if (relu) { v0 = fmaxf(v0, 0.f); v1 = fmaxf(v1, 0.f); }
                        __half2 hv2 = __floats2half2_rn(v0, v1);
                        *(__half2*)&C[(size_t)m * Nc + n] = hv2;
                        if (att_s)
                            *(__half2*)&stage[(m - row0) * SPITCH + n] = hv2;
                        acc[tm][tn][hf * 2] = 0.f;
                        acc[tm][tn][hf * 2 + 1] = 0.f;
                    }
                }
        }
    }

    if (att_s) {
        __syncthreads();
        const __half* stage = smh;
        for (int task = tid; task < 128 * HH; task += 256) {
            int r = task >> 3, h = task & 7;
            int gn = row0 + r;
            if (gn >= M) continue;
            const __half2* xr = (const __half2*)&stage[r * SPITCH + h * DVC];
            float s = 0.f, d = 0.f;
            #pragma unroll
            for (int c = 0; c < DVC / 2; c++) {
                float2 v = __half22float2(xr[c]);
                s += v.x * att_s[h * DVC + 2 * c] + v.y * att_s[h * DVC + 2 * c + 1];
                d += v.x * att_d[h * DVC + 2 * c] + v.y * att_d[h * DVC + 2 * c + 1];
            }
            float2 sp; sp.x = s; sp.y = __expf(s);
            float2 dp; dp.x = d; dp.y = __expf(d);
            g_asf[gn * HH + h] = sp;
            g_adf[gn * HH + h] = dp;
        }
    }
}

// ---------------- streaming fp16 GEMM (lin3, K=512), 3-stage, fused BN2 stats ----------------
__global__ void __launch_bounds__(256) k_hgemm(
        const __half* __restrict__ A, const __half* __restrict__ Bh,
        const float* __restrict__ bias, const float* __restrict__ resf,
        float* __restrict__ Cf, int M, int Nc, int K) {
    extern __shared__ __half smh[];
    __shared__ float ssum[128], ssq[128];
    int tid = threadIdx.x, lane = tid & 31, wid = tid >> 5;
    int wm = wid & 3, wn = wid >> 2;
    int row0 = blockIdx.x * 128, col0 = blockIdx.y * 128;
    int g = lane >> 2, t4 = lane & 3;

    if (tid < 128) { ssum[tid] = 0.f; ssq[tid] = 0.f; }

    int a_row = lane & 15;
    int a_koff = (lane >> 4) << 3;
    int b_nloc = (lane & 7) + ((lane & 16) ? 8 : 0);
    int b_koff = (lane & 8) ? 8 : 0;

    float acc[2][8][4];
    #pragma unroll
    for (int i = 0; i < 2; i++)
        #pragma unroll
        for (int j = 0; j < 8; j++)
            #pragma unroll
            for (int q = 0; q < 4; q++) acc[i][j][q] = 0.f;

    const int nch = K / 32;

    auto prefetch = [&](int ch, int st) {
        int kk = ch * 32;
        for (int tile = 0; tile < 2; tile++) {
            const __half* gp = tile == 0 ? A : Bh;
            bool isA = tile == 0;
            __half* sbase = smh + (st * 2 + tile) * TILEE;
            #pragma unroll
            for (int it = 0; it < 2; it++) {
                int id = it * 256 + tid;
                int m = id >> 2, ko = (id & 3) << 3;
                int gm = (isA ? row0 : col0) + m;
                int sz = 16;
                if (isA && gm >= M) { gm = 0; sz = 0; }
                cpasync16(sm32(sbase + m * LDK + ko), gp + (size_t)gm * K + kk + ko, sz);
            }
        }
        cpcommit();
    };

    prefetch(0, 0);
    if (nch > 1) prefetch(1, 1);
    for (int ch = 0; ch < nch; ch++) {
        int st = ch % 3;
        if (ch + 2 < nch) { prefetch(ch + 2, (ch + 2) % 3); cpwait<2>(); }
        else if (ch + 1 < nch) cpwait<1>();
        else cpwait<0>();
        __syncthreads();
        const __half* sA  = smh + (st * 2 + 0) * TILEE;
        const __half* sBh = smh + (st * 2 + 1) * TILEE;
        #pragma unroll
        for (int ks = 0; ks < 2; ks++) {
            int c = ks * 16;
            uint32_t ar[2][4];
            #pragma unroll
            for (int tm = 0; tm < 2; tm++) {
                int r = wm * 32 + tm * 16 + a_row;
                ldsm4(ar[tm], sm32(&sA[r * LDK + c + a_koff]));
            }
            uint32_t bh[4][4];
            #pragma unroll
            for (int q = 0; q < 4; q++) {
                int n = wn * 64 + q * 16 + b_nloc;
                ldsm4(bh[q], sm32(&sBh[n * LDK + c + b_koff]));
            }
            #pragma unroll
            for (int q = 0; q < 4; q++)
                #pragma unroll
                for (int sub = 0; sub < 2; sub++)
                    #pragma unroll
                    for (int tm = 0; tm < 2; tm++)
                        mma16816h(acc[tm][q * 2 + sub], ar[tm], &bh[q][sub * 2]);
        }
        __syncthreads();
    }

    #pragma unroll
    for (int tn = 0; tn < 8; tn++) {
        int n = col0 + wn * 64 + tn * 8 + 2 * t4;
        float s0 = 0.f, s1 = 0.f, q0 = 0.f, q1 = 0.f;
        #pragma unroll
        for (int tm = 0; tm < 2; tm++)
            #pragma unroll
            for (int hf = 0; hf < 2; hf++) {
                int m = row0 + wm * 32 + tm * 16 + g + hf * 8;
                if (m >= M) continue;
                float v0 = acc[tm][tn][hf * 2] + bias[n];
                float v1 = acc[tm][tn][hf * 2 + 1] + bias[n + 1];
                const float2 rv = *(const float2*)&resf[(size_t)m * Nc + n];
                v0 += rv.x; v1 += rv.y;
                float2 o; o.x = v0; o.y = v1;
                *(float2*)&Cf[(size_t)m * Nc + n] = o;
                s0 += v0; s1 += v1;
                q0 += v0 * v0; q1 += v1 * v1;
            }
        #pragma unroll
        for (int mk = 4; mk <= 16; mk <<= 1) {
            s0 += __shfl_xor_sync(0xFFFFFFFFu, s0, mk);
            s1 += __shfl_xor_sync(0xFFFFFFFFu, s1, mk);
            q0 += __shfl_xor_sync(0xFFFFFFFFu, q0, mk);
            q1 += __shfl_xor_sync(0xFFFFFFFFu, q1, mk);
        }
        if (lane < 4) {
            int cl = wn * 64 + tn * 8 + 2 * t4;
            atomicAdd(&ssum[cl], s0);
            atomicAdd(&ssum[cl + 1], s1);
            atomicAdd(&ssq[cl], q0);
            atomicAdd(&ssq[cl + 1], q1);
        }
    }
    __syncthreads();
    if (tid < 128) {
        atomicAdd(&g_sum2[col0 + tid], ssum[tid]);
        atomicAdd(&g_sumsq2[col0 + tid], ssq[tid]);
    }
}

// ---------------- edge weights ----------------
__global__ void k_ew() {
    int idx = blockIdx.x * blockDim.x + threadIdx.x;
    if (idx >= ET * HH) return;
    int p = idx >> 3, h = idx & 7;
    int s = g_csr[p], d = g_dste[p];
    float2 A = g_asf[s * HH + h];
    float2 B = g_adf[d * HH + h];
    float v = A.x + B.x;
    float w = (v > 0.f) ? A.y * B.y : __expf(NEG * v);
    g_wh[idx] = __float2half(w);
}

// ---------------- GAT aggregate: warp-per-node ----------------
// lane l owns dims 4l..4l+3 (head = l>>2); head-sum via shfl_xor over head bits.
__global__ void __launch_bounds__(256) k_gat(const float* __restrict__ lin1w) {
    int w = (blockIdx.x * 256 + threadIdx.x) >> 5;
    if (w >= NN) return;
    int lane = threadIdx.x & 31;
    int n = w;
    int hh = lane >> 2;
    int s = g_off[n], e = g_off[n + 1];
    const uint2* x2 = (const uint2*)g_xlh;

    float4 acc = make_float4(0.f, 0.f, 0.f, 0.f);
    float sum = 0.f;
    int p = s;
    #pragma unroll 1
    for (; p + 4 <= e; p += 4) {
        int j[4];
        #pragma unroll
        for (int q = 0; q < 4; q++) j[q] = g_csr[p + q];
        float wt[4];
        #pragma unroll
        for (int q = 0; q < 4; q++) wt[q] = __half2float(g_wh[(p + q) * HH + hh]);
        uint2 u[4];
        #pragma unroll
        for (int q = 0; q < 4; q++) u[q] = x2[(size_t)j[q] * 32 + lane];
        #pragma unroll
        for (int q = 0; q < 4; q++) {
            float2 a = __half22float2(*(__half2*)&u[q].x);
            float2 b = __half22float2(*(__half2*)&u[q].y);
            acc.x += wt[q] * a.x; acc.y += wt[q] * a.y;
            acc.z += wt[q] * b.x; acc.w += wt[q] * b.y;
            sum += wt[q];
        }
    }
    for (; p < e; p++) {
        int j = g_csr[p];
        float wt = __half2float(g_wh[p * HH + hh]);
        uint2 u = x2[(size_t)j * 32 + lane];
        float2 a = __half22float2(*(__half2*)&u.x);
        float2 b = __half22float2(*(__half2*)&u.y);
        acc.x += wt * a.x; acc.y += wt * a.y;
        acc.z += wt * b.x; acc.w += wt * b.y;
        sum += wt;
    }
    float inv = 1.f / sum;
    acc.x *= inv; acc.y *= inv; acc.z *= inv; acc.w *= inv;

    // head-sum over lanes differing in head bits (2,3,4)
    #pragma unroll
    for (int mk = 4; mk <= 16; mk <<= 1) {
        acc.x += __shfl_xor_sync(0xFFFFFFFFu, acc.x, mk);
        acc.y += __shfl_xor_sync(0xFFFFFFFFu, acc.y, mk);
        acc.z += __shfl_xor_sync(0xFFFFFFFFu, acc.z, mk);
        acc.w += __shfl_xor_sync(0xFFFFFFFFu, acc.w, mk);
    }
    // lane (l&3)==src holds gs[4*src .. 4*src+3]; broadcast full 16-vector
    float gs[16];
    #pragma unroll
    for (int src = 0; src < 4; src++) {
        int sl = (lane & 28) | src;
        gs[src * 4 + 0] = __shfl_sync(0xFFFFFFFFu, acc.x, sl);
        gs[src * 4 + 1] = __shfl_sync(0xFFFFFFFFu, acc.y, sl);
        gs[src * 4 + 2] = __shfl_sync(0xFFFFFFFFu, acc.z, sl);
        gs[src * 4 + 3] = __shfl_sync(0xFFFFFFFFu, acc.w, sl);
    }
    // lin1 + residual, 4 output columns per lane
    int col = 4 * lane;
    float4 hp = ((const float4*)g_h)[(size_t)n * 32 + lane];
    float o0 = hp.x, o1 = hp.y, o2 = hp.z, o3 = hp.w;
    #pragma unroll
    for (int c = 0; c < DVC; c++) {
        const float* wr = &lin1w[c * D + col];
        float gc = gs[c];
        o0 += gc * wr[0];
        o1 += gc * wr[1];
        o2 += gc * wr[2];
        o3 += gc * wr[3];
    }
    float4 o; o.x = o0; o.y = o1; o.z = o2; o.w = o3;
    ((float4*)g_tmp)[(size_t)n * 32 + lane] = o;
}

// ---------------- BatchNorm ----------------
__global__ void k_bnstats(const float* __restrict__ z) {
    int t = threadIdx.x;
    float s = 0.f, q = 0.f;
    for (int n = blockIdx.x; n < NN; n += gridDim.x) {
        float v = z[n * D + t];
        s += v;
        q += v * v;
    }
    atomicAdd(&g_sum[t], s);
    atomicAdd(&g_sumsq[t], q);
}

__global__ void k_bnapply1(const float* __restrict__ z, const float* __restrict__ g,
                           const float* __restrict__ b, float* __restrict__ h1f) {
    int i = blockIdx.x * blockDim.x + threadIdx.x;
    if (i < D) { g_sum2[i] = 0.f; g_sumsq2[i] = 0.f; }
    if (i >= NN * D) return;
    int d = i & 127;
    const float invn = 1.f / (float)NN;
    float mu = g_sum[d] * invn;
    float var = g_sumsq[d] * invn - mu * mu;
    float v = g[d] * (z[i] - mu) * rsqrtf(var + BNEPS) + b[d];
    g_h116[i] = __float2half(v);
    h1f[i] = v;
}

__global__ void k_bnapply2(const float* __restrict__ z, const float* __restrict__ g,
                           const float* __restrict__ b, float* __restrict__ out,
                           __half* __restrict__ oh, __half* __restrict__ yh) {
    int i = blockIdx.x * blockDim.x + threadIdx.x;
    if (i >= NN * D) return;
    int d = i & 127;
    const float invn = 1.f / (float)NN;
    float mu = g_sum2[d] * invn;
    float var = g_sumsq2[d] * invn - mu * mu;
    float v = g[d] * (z[i] - mu) * rsqrtf(var + BNEPS) + b[d];
    out[i] = v;
    if (oh) oh[i] = __float2half(v);
    if (yh) yh[i] = __float2half(g_dinv[i >> 7] * v);
}

// ---------------- APPNP ----------------
__global__ void __launch_bounds__(256) k_appnp_h(const __half* __restrict__ yin,
                                                 __half* __restrict__ yout,
                                                 const float* __restrict__ J,
                                                 float* __restrict__ outp) {
    int w = (blockIdx.x * 256 + threadIdx.x) >> 5;
    if (w >= NN) return;
    int lane = threadIdx.x & 31;
    int n = w;
    int s = g_off[n], e = g_off[n + 1];
    const uint2* y2 = (const uint2*)yin;
    float4 acc = make_float4(0.f, 0.f, 0.f, 0.f);
    int p = s;
    #pragma unroll 1
    for (; p + 8 <= e; p += 8) {
        int j[8];
        #pragma unroll
        for (int q = 0; q < 8; q++) j[q] = g_csr[p + q];
        uint2 u[8];
        #pragma unroll
        for (int q = 0; q < 8; q++) u[q] = y2[(size_t)j[q] * 32 + lane];
        #pragma unroll
        for (int q = 0; q < 8; q++) {
            float2 a = __half22float2(*(__half2*)&u[q].x);
            float2 b = __half22float2(*(__half2*)&u[q].y);
            acc.x += a.x; acc.y += a.y; acc.z += b.x; acc.w += b.y;
        }
    }
    if (p + 4 <= e) {
        int j[4];
        #pragma unroll
        for (int q = 0; q < 4; q++) j[q] = g_csr[p + q];
        uint2 u[4];
        #pragma unroll
        for (int q = 0; q < 4; q++) u[q] = y2[(size_t)j[q] * 32 + lane];
        #pragma unroll
        for (int q = 0; q < 4; q++) {
            float2 a = __half22float2(*(__half2*)&u[q].x);
            float2 b = __half22float2(*(__half2*)&u[q].y);
            acc.x += a.x; acc.y += a.y; acc.z += b.x; acc.w += b.y;
        }
        p += 4;
    }
    for (; p < e; p++) {
        int j = g_csr[p];
        uint2 u = y2[(size_t)j * 32 + lane];
        float2 a = __half22float2(*(__half2*)&u.x);
        float2 b = __half22float2(*(__half2*)&u.y);
        acc.x += a.x; acc.y += a.y; acc.z += b.x; acc.w += b.y;
    }
    float di = g_dinv[n];
    float sc = 0.9f * di;
    float4 h0 = ((const float4*)g_h)[(size_t)n * 32 + lane];
    float4 hv;
    hv.x = sc * acc.x + 0.1f * h0.x;
    hv.y = sc * acc.y + 0.1f * h0.y;
    hv.z = sc * acc.z + 0.1f * h0.z;
    hv.w = sc * acc.w + 0.1f * h0.w;
    if (outp) {
        size_t base = (size_t)n * (D + 1) + 4 * lane;
        outp[base + 0] = hv.x;
        outp[base + 1] = hv.y;
        outp[base + 2] = hv.z;
        outp[base + 3] = hv.w;
        if (lane == 0) outp[(size_t)n * (D + 1) + D] = J[n];
    } else {
        uint2 o;
        *(__half2*)&o.x = __floats2half2_rn(di * hv.x, di * hv.y);
        *(__half2*)&o.y = __floats2half2_rn(di * hv.z, di * hv.w);
        ((uint2*)yout)[(size_t)n * 32 + lane] = o;
    }
}

// ---------------- orchestration ----------------
extern "C" void kernel_launch(void* const* d_in, const int* in_sizes, int n_in,
                              void* d_out, int out_size) {
    const float* x      = (const float*)d_in[0];
    const float* J      = (const float*)d_in[1];
    const int*   ei     = (const int*)d_in[2];
    const float* lin0_w = (const float*)d_in[3];
    const float* lin0_b = (const float*)d_in[4];
    const float* gat_w  = (const float*)d_in[5];
    const float* att_src= (const float*)d_in[6];
    const float* att_dst= (const float*)d_in[7];
    const float* lin1_w = (const float*)d_in[8];
    const float* bn1_g  = (const float*)d_in[9];
    const float* bn1_b  = (const float*)d_in[10];
    const float* lin2_w = (const float*)d_in[11];
    const float* lin2_b = (const float*)d_in[12];
    const float* lin3_w = (const float*)d_in[13];
    const float* lin3_b = (const float*)d_in[14];
    const float* bn2_g  = (const float*)d_in[15];
    const float* bn2_b  = (const float*)d_in[16];
    float* out = (float*)d_out;

    float *ph, *ptmp;
    cudaGetSymbolAddress((void**)&ph, g_h);
    cudaGetSymbolAddress((void**)&ptmp, g_tmp);
    __half *ph16, *pxlh, *pya, *pyb, *ph116, *phid16;
    __half *pwxh, *pwxl, *pw2h, *pw3h;
    cudaGetSymbolAddress((void**)&ph16, g_h16);
    cudaGetSymbolAddress((void**)&pxlh, g_xlh);
    cudaGetSymbolAddress((void**)&pya, g_ya);
    cudaGetSymbolAddress((void**)&pyb, g_yb);
    cudaGetSymbolAddress((void**)&ph116, g_h116);
    cudaGetSymbolAddress((void**)&phid16, g_hid16);
    cudaGetSymbolAddress((void**)&pwxh, g_wxh);
    cudaGetSymbolAddress((void**)&pwxl, g_wxl);
    cudaGetSymbolAddress((void**)&pw2h, g_w2h);
    cudaGetSymbolAddress((void**)&pw3h, g_w3h);

    static bool attrset = false;
    const int GSMA = (4 + 4) * TILEE * (int)sizeof(__half);
    const int GSMA1 = (4 + 2) * TILEE * (int)sizeof(__half);
    const int GSMS = 3 * 2 * TILEE * (int)sizeof(__half);
    if (!attrset) {
        cudaFuncSetAttribute(k_hgemm_ares, cudaFuncAttributeMaxDynamicSharedMemorySize, GSMA);
        cudaFuncSetAttribute(k_hgemm, cudaFuncAttributeMaxDynamicSharedMemorySize, GSMS);
        attrset = true;
    }

    const int MB = (NN + 127) / 128;  // 391
    const int DD = D * D, DHD = D * DHID;
    const int CONVW_TOT = 2 * DD + 4 * DHD;

    // slots 1-4 arranged so profiled launch #4 = xl GEMM (+ fused attdot)
    k_lin0<<<(NN * D + 255) / 256, 256>>>(x, J, lin0_w, lin0_b);      // also zeroes g_cnt
    k_convw_all<<<(CONVW_TOT + 255) / 256, 256>>>(gat_w, lin2_w, lin3_w);
    k_count<<<(EE + 255) / 256, 256>>>(ei);
    k_hgemm_ares<<<MB, 256, GSMA>>>(ph16, pwxh, pwxl, nullptr, pxlh,
                                    att_src, att_dst, NN, D, D, 0, 1);

    k_scan1<<<SCNB, SCB>>>();
    k_scan2<<<1, 256>>>();
    k_scan3<<<SCNB, SCB>>>();
    k_fill<<<(ET + 255) / 256, 256>>>(ei);

    for (int l = 0; l < 2; l++) {
        if (l == 1) {
            k_hgemm_ares<<<MB, 256, GSMA>>>(ph16, pwxh + DD, pwxl + DD, nullptr, pxlh,
                                            att_src + HH * DVC, att_dst + HH * DVC,
                                            NN, D, D, 0, 1);
        }
        k_ew<<<(ET * HH + 255) / 256, 256>>>();
        k_gat<<<(NN * 32 + 255) / 256, 256>>>(lin1_w + (size_t)l * DVC * D);
        k_bnstats<<<512, 128>>>(ptmp);
        k_bnapply1<<<(NN * D + 255) / 256, 256>>>(ptmp, bn1_g + l * D, bn1_b + l * D, ptmp);
        k_hgemm_ares<<<MB, 256, GSMA1>>>(ph116, pw2h + (size_t)l * DHD, nullptr,
                                         lin2_b + l * DHID, phid16,
                                         nullptr, nullptr, NN, DHID, D, 1, 4);
        k_hgemm<<<dim3(MB, 1), 256, GSMS>>>(phid16, pw3h + (size_t)l * DHD,
                                            lin3_b + l * D, ptmp, ptmp,
                                            NN, D, DHID);
        if (l == 0)
            k_bnapply2<<<(NN * D + 255) / 256, 256>>>(ptmp, bn2_g + l * D, bn2_b + l * D,
                                                      ph, ph16, nullptr);
        else
            k_bnapply2<<<(NN * D + 255) / 256, 256>>>(ptmp, bn2_g + l * D, bn2_b + l * D,
                                                      ph, nullptr, pya);
    }

    for (int k = 0; k < 10; k++) {
        const __half* yi = (k & 1) ? pyb : pya;
        __half* yo = (k & 1) ? pya : pyb;
        if (k < 9)
            k_appnp_h<<<(NN * 32 + 255) / 256, 256>>>(yi, yo, nullptr, nullptr);
        else
            k_appnp_h<<<(NN * 32 + 255) / 256, 256>>>(yi, nullptr, J, out);
    }
    (void)in_sizes; (void)n_in; (void)out_size;
}